// round 4
// baseline (speedup 1.0000x reference)
#include <cuda_runtime.h>
#include <math.h>

#define NN 50000
#define DD 128
#define EE 800000
#define ET (EE + NN)

#define TM 64
#define TN 256
#define KP 132
#define NTILES ((NN + TM - 1) / TM)      // 782
#define GEMM_SMEM ((TM + TN) * KP * 4)   // 168960 B
#define GEMM_GRID 148

#define SCB 1024
#define NBLK ((NN + SCB - 1) / SCB)

// Scratch (allocation-free rule: __device__ globals)
__device__ float g_xl[NN * DD];
__device__ float g_xr[NN * DD];
__device__ float g_h[NN * DD];
__device__ int g_rowptr[NN + 1];
__device__ int g_deg[NN];
__device__ int g_fill[NN];
__device__ int g_srcs[ET];
__device__ int g_part[NBLK];
__device__ int g_is64;

// ---------------------------------------------------------------------------
__global__ void k_init(const void* e) {                              // launch 1
    int i = blockIdx.x * blockDim.x + threadIdx.x;
    if (i < NN) { g_deg[i] = 0; g_fill[i] = 0; }
    if (i == 0) {
        const long long* p = (const long long*)e;
        int ok = 1;
        for (int q = 0; q < 16; q++) {
            long long v = p[q];
            if (v < 0 || v >= NN) ok = 0;
        }
        g_is64 = ok;
        g_rowptr[NN] = ET;
    }
}

__device__ __forceinline__ int load_idx(const void* e, long long pos, int is64) {
    return is64 ? (int)((const long long*)e)[pos] : ((const int*)e)[pos];
}

__global__ void k_hist(const void* __restrict__ eidx) {              // launch 2
    int e = blockIdx.x * blockDim.x + threadIdx.x;
    if (e >= ET) return;
    int is64 = g_is64;
    int dst = (e < EE) ? load_idx(eidx, (long long)EE + e, is64) : (e - EE);
    atomicAdd(&g_deg[dst], 1);
}

__global__ void k_scan1() {                                          // launch 3
    __shared__ int wsum[32];
    int i = blockIdx.x * SCB + threadIdx.x;
    int lane = threadIdx.x & 31, wid = threadIdx.x >> 5;
    int v = (i < NN) ? g_deg[i] : 0;
#pragma unroll
    for (int o = 1; o < 32; o <<= 1) v += __shfl_down_sync(~0u, v, o);
    if (lane == 0) wsum[wid] = v;
    __syncthreads();
    if (wid == 0) {
        int s = wsum[lane];
#pragma unroll
        for (int o = 1; o < 32; o <<= 1) s += __shfl_down_sync(~0u, s, o);
        if (lane == 0) g_part[blockIdx.x] = s;
    }
}

__global__ void k_scan2() {                                          // launch 5
    __shared__ int wsum[32];
    __shared__ int sbase;
    int i = blockIdx.x * SCB + threadIdx.x;
    int lane = threadIdx.x & 31, wid = threadIdx.x >> 5;

    if (wid == 0) {
        int b = 0;
        for (int t = lane; t < NBLK; t += 32)
            if (t < blockIdx.x) b += g_part[t];
#pragma unroll
        for (int o = 1; o < 32; o <<= 1) b += __shfl_down_sync(~0u, b, o);
        if (lane == 0) sbase = b;
    }

    int v0 = (i < NN) ? g_deg[i] : 0;
    int v = v0;
#pragma unroll
    for (int o = 1; o < 32; o <<= 1) {
        int n = __shfl_up_sync(~0u, v, o);
        if (lane >= o) v += n;
    }
    if (lane == 31) wsum[wid] = v;
    __syncthreads();
    if (wid == 0) {
        int s = wsum[lane];
#pragma unroll
        for (int o = 1; o < 32; o <<= 1) {
            int n = __shfl_up_sync(~0u, s, o);
            if (lane >= o) s += n;
        }
        wsum[lane] = s;
    }
    __syncthreads();
    int excl = v - v0 + (wid ? wsum[wid - 1] : 0);
    if (i < NN) g_rowptr[i] = sbase + excl;
}

__global__ void k_scatter(const void* __restrict__ eidx) {           // launch 6
    int e = blockIdx.x * blockDim.x + threadIdx.x;
    if (e >= ET) return;
    int is64 = g_is64;
    int s, d;
    if (e < EE) {
        s = load_idx(eidx, e, is64);
        d = load_idx(eidx, (long long)EE + e, is64);
    } else {
        s = d = e - EE;
    }
    int pos = atomicAdd(&g_fill[d], 1);
    g_srcs[g_rowptr[d] + pos] = s;
}

// ---------------------------------------------------------------------------
// Persistent fused GEMM: xl = h @ Wl^T, xr = h @ Wr^T. W loaded once/block.
// ---------------------------------------------------------------------------
typedef unsigned long long u64;

__device__ __forceinline__ void ffma2(u64& acc, u64 a, u64 b) {
    asm("fma.rn.f32x2 %0, %1, %2, %0;" : "+l"(acc) : "l"(a), "l"(b));
}

__global__ void __launch_bounds__(256, 1)
k_gemm(const float* __restrict__ hin,
       const float* __restrict__ Wl,
       const float* __restrict__ Wr) {
    extern __shared__ float sm[];
    float* xs = sm;             // [TM][KP]
    float* ws = sm + TM * KP;   // [TN][KP]

    const int tid = threadIdx.x;
    const int lane = tid & 31;
    const int warp = tid >> 5;

    // Load W once (both matrices), row-major
    for (int idx = tid; idx < TN * 32; idx += 256) {
        int r = idx >> 5, c4 = idx & 31;
        const float* wsrc = (r < DD) ? (Wl + (size_t)r * DD) : (Wr + (size_t)(r - DD) * DD);
        float4 g = *(const float4*)(wsrc + c4 * 4);
        *(float4*)(ws + r * KP + c4 * 4) = g;
    }

    const int warp_m = warp >> 2;
    const int warp_n = warp & 3;
    const int lane_m = lane >> 3;
    const int lane_n = lane & 7;
    const int rbase = warp_m * 32 + lane_m;   // rows rbase + 4*i
    const int jbase = warp_n * 64 + lane_n;   // cols jbase + 8*j
    const bool isL = (warp_n < 2);
    float* outp = isL ? g_xl : g_xr;
    const int cb = jbase - (isL ? 0 : DD);

    for (int tile = blockIdx.x; tile < NTILES; tile += GEMM_GRID) {
        const int row0 = tile * TM;

        for (int idx = tid; idx < TM * 32; idx += 256) {
            int r = idx >> 5, c4 = idx & 31;
            int row = row0 + r;
            float4 g = make_float4(0.f, 0.f, 0.f, 0.f);
            if (row < NN) g = *(const float4*)(hin + (size_t)row * DD + c4 * 4);
            *(float4*)(xs + r * KP + c4 * 4) = g;
        }
        __syncthreads();

        u64 acc[8][8];
#pragma unroll
        for (int i = 0; i < 8; i++)
#pragma unroll
            for (int j = 0; j < 8; j++) acc[i][j] = 0ull;

        const float* xp = xs + rbase * KP;
        const float* wp = ws + jbase * KP;

#pragma unroll 2
        for (int k = 0; k < DD; k += 4) {
            ulonglong2 a2[8], b2[8];
#pragma unroll
            for (int i = 0; i < 8; i++)
                a2[i] = *(const ulonglong2*)(xp + i * 4 * KP + k);
#pragma unroll
            for (int j = 0; j < 8; j++)
                b2[j] = *(const ulonglong2*)(wp + j * 8 * KP + k);
#pragma unroll
            for (int i = 0; i < 8; i++)
#pragma unroll
                for (int j = 0; j < 8; j++) {
                    ffma2(acc[i][j], a2[i].x, b2[j].x);
                    ffma2(acc[i][j], a2[i].y, b2[j].y);
                }
        }
        __syncthreads();   // all mainloop reads of xs done before next tile load

#pragma unroll
        for (int i = 0; i < 8; i++) {
            int row = row0 + rbase + i * 4;
            if (row < NN) {
                float* orow = outp + (size_t)row * DD;
#pragma unroll
                for (int j = 0; j < 8; j++) {
                    float2 s = *(float2*)&acc[i][j];
                    orow[cb + j * 8] = s.x + s.y;
                }
            }
        }
    }
}

// ---------------------------------------------------------------------------
// GATv2 aggregation: warp/node, online softmax with rare rescale,
// 4-edge groups with 10-shfl packed reduction.
// ---------------------------------------------------------------------------
__device__ __forceinline__ float gelu_exact(float x) {
    return 0.5f * x * (1.f + erff(x * 0.70710678118654752440f));
}

__device__ __forceinline__ float wsum32(float e) {
    e += __shfl_xor_sync(0xffffffffu, e, 16);
    e += __shfl_xor_sync(0xffffffffu, e, 8);
    e += __shfl_xor_sync(0xffffffffu, e, 4);
    e += __shfl_xor_sync(0xffffffffu, e, 2);
    e += __shfl_xor_sync(0xffffffffu, e, 1);
    return e;
}

__global__ void __launch_bounds__(256)
k_agg(const float* __restrict__ att,
      const float* __restrict__ bias,
      float* __restrict__ hout) {
    const int gw = (blockIdx.x * blockDim.x + threadIdx.x) >> 5;
    const int lane = threadIdx.x & 31;
    if (gw >= NN) return;
    const int d4 = lane * 4;

    const float4 xr4 = *(const float4*)(g_xr + (size_t)gw * DD + d4);
    const float4 at4 = *(const float4*)(att + d4);

    const int p0 = g_rowptr[gw];
    const int p1 = g_rowptr[gw + 1];

    float m = __int_as_float(0xff800000);  // -inf
    float denom = 0.f;
    float ax = 0.f, ay = 0.f, az = 0.f, aw = 0.f;

    const bool b0 = (lane & 1);
    const bool b1 = (lane & 2);

    int p = p0;
    for (; p + 4 <= p1; p += 4) {
        float4 v[4];
        float e[4];
#pragma unroll
        for (int q = 0; q < 4; q++) {
            int s = __ldg(&g_srcs[p + q]);
            v[q] = *(const float4*)(g_xl + (size_t)s * DD + d4);
            float t0 = v[q].x + xr4.x; t0 = t0 > 0.f ? t0 : 0.2f * t0;
            float t1 = v[q].y + xr4.y; t1 = t1 > 0.f ? t1 : 0.2f * t1;
            float t2 = v[q].z + xr4.z; t2 = t2 > 0.f ? t2 : 0.2f * t2;
            float t3 = v[q].w + xr4.w; t3 = t3 > 0.f ? t3 : 0.2f * t3;
            e[q] = t0 * at4.x + t1 * at4.y + t2 * at4.z + t3 * at4.w;
        }
        // packed 4-way warp reduction: 10 SHFL instead of 20
        float s01 = b0 ? e[0] : e[1];
        float r01 = __shfl_xor_sync(~0u, s01, 1);
        float a01 = (b0 ? e[1] : e[0]) + r01;     // even: e0 pair, odd: e1 pair
        float s23 = b0 ? e[2] : e[3];
        float r23 = __shfl_xor_sync(~0u, s23, 1);
        float a23 = (b0 ? e[3] : e[2]) + r23;     // even: e2 pair, odd: e3 pair
        float sB = b1 ? a01 : a23;
        float rB = __shfl_xor_sync(~0u, sB, 2);
        float c = (b1 ? a23 : a01) + rB;          // lane&3==q holds e_q quad
        c += __shfl_xor_sync(~0u, c, 4);
        c += __shfl_xor_sync(~0u, c, 8);
        c += __shfl_xor_sync(~0u, c, 16);
        e[0] = __shfl_sync(~0u, c, 0);
        e[1] = __shfl_sync(~0u, c, 1);
        e[2] = __shfl_sync(~0u, c, 2);
        e[3] = __shfl_sync(~0u, c, 3);

#pragma unroll
        for (int q = 0; q < 4; q++) {
            if (e[q] > m) {                        // warp-uniform, rare
                float corr = __expf(m - e[q]);
                m = e[q];
                denom *= corr; ax *= corr; ay *= corr; az *= corr; aw *= corr;
            }
            float w = __expf(e[q] - m);
            denom += w;
            ax += w * v[q].x;
            ay += w * v[q].y;
            az += w * v[q].z;
            aw += w * v[q].w;
        }
    }
    for (; p < p1; p++) {
        int s = __ldg(&g_srcs[p]);
        const float4 vv = *(const float4*)(g_xl + (size_t)s * DD + d4);
        float t0 = vv.x + xr4.x; t0 = t0 > 0.f ? t0 : 0.2f * t0;
        float t1 = vv.y + xr4.y; t1 = t1 > 0.f ? t1 : 0.2f * t1;
        float t2 = vv.z + xr4.z; t2 = t2 > 0.f ? t2 : 0.2f * t2;
        float t3 = vv.w + xr4.w; t3 = t3 > 0.f ? t3 : 0.2f * t3;
        float e = wsum32(t0 * at4.x + t1 * at4.y + t2 * at4.z + t3 * at4.w);
        if (e > m) {
            float corr = __expf(m - e);
            m = e;
            denom *= corr; ax *= corr; ay *= corr; az *= corr; aw *= corr;
        }
        float w = __expf(e - m);
        denom += w;
        ax += w * vv.x;
        ay += w * vv.y;
        az += w * vv.z;
        aw += w * vv.w;
    }

    const float inv = 1.f / denom;
    const float4 b4 = *(const float4*)(bias + d4);
    float4 o;
    o.x = gelu_exact(ax * inv + b4.x);
    o.y = gelu_exact(ay * inv + b4.y);
    o.z = gelu_exact(az * inv + b4.z);
    o.w = gelu_exact(aw * inv + b4.w);
    *(float4*)(hout + (size_t)gw * DD + d4) = o;
}

// ---------------------------------------------------------------------------
extern "C" void kernel_launch(void* const* d_in, const int* in_sizes, int n_in,
                              void* d_out, int out_size) {
    const float* x = (const float*)d_in[0];
    const void* eidx = d_in[1];
    const float* Wl[3] = {(const float*)d_in[2], (const float*)d_in[6], (const float*)d_in[10]};
    const float* Wr[3] = {(const float*)d_in[3], (const float*)d_in[7], (const float*)d_in[11]};
    const float* at[3] = {(const float*)d_in[4], (const float*)d_in[8], (const float*)d_in[12]};
    const float* bi[3] = {(const float*)d_in[5], (const float*)d_in[9], (const float*)d_in[13]};

    void* p_h_v = nullptr;
    cudaGetSymbolAddress(&p_h_v, g_h);
    float* p_h = (float*)p_h_v;

    cudaFuncSetAttribute(k_gemm, cudaFuncAttributeMaxDynamicSharedMemorySize, GEMM_SMEM);

    // Launch order puts k_gemm (layer 0) at position 4 => it gets profiled.
    k_init<<<(NN + 255) / 256, 256>>>(eidx);                          // 1
    k_hist<<<(ET + 255) / 256, 256>>>(eidx);                          // 2
    k_scan1<<<NBLK, SCB>>>();                                         // 3
    k_gemm<<<GEMM_GRID, 256, GEMM_SMEM>>>(x, Wl[0], Wr[0]);           // 4 (profiled)
    k_scan2<<<NBLK, SCB>>>();                                         // 5
    k_scatter<<<(ET + 255) / 256, 256>>>(eidx);                       // 6

    k_agg<<<(NN * 32 + 255) / 256, 256>>>(at[0], bi[0], p_h);         // 7

    for (int l = 1; l < 3; l++) {
        const float* hin = p_h;
        float* hout = (l == 2) ? (float*)d_out : p_h;
        k_gemm<<<GEMM_GRID, 256, GEMM_SMEM>>>(hin, Wl[l], Wr[l]);
        k_agg<<<(NN * 32 + 255) / 256, 256>>>(at[l], bi[l], hout);
    }
}

// round 5
// speedup vs baseline: 1.4238x; 1.4238x over previous
#include <cuda_runtime.h>
#include <math.h>

#define NN 50000
#define DD 128
#define EE 800000
#define ET (EE + NN)

#define TM 64
#define TN 256
#define KP 132
#define NTILES ((NN + TM - 1) / TM)      // 782
#define GEMM_SMEM ((TM + TN) * KP * 4)   // 168960 B
#define GEMM_GRID 148
#define GEMM_THREADS 512

#define SCB 1024
#define NBLK ((NN + SCB - 1) / SCB)

// Scratch (allocation-free rule: __device__ globals)
__device__ float g_xl[NN * DD];
__device__ float g_xr[NN * DD];
__device__ float g_h[NN * DD];
__device__ int g_rowptr[NN + 1];
__device__ int g_deg[NN];
__device__ int g_fill[NN];
__device__ int g_srcs[ET];
__device__ int g_part[NBLK];
__device__ int g_is64;

// ---------------------------------------------------------------------------
__global__ void k_init(const void* e) {                              // launch 1
    int i = blockIdx.x * blockDim.x + threadIdx.x;
    if (i < NN) { g_deg[i] = 0; g_fill[i] = 0; }
    if (i == 0) {
        const long long* p = (const long long*)e;
        int ok = 1;
        for (int q = 0; q < 16; q++) {
            long long v = p[q];
            if (v < 0 || v >= NN) ok = 0;
        }
        g_is64 = ok;
        g_rowptr[NN] = ET;
    }
}

__device__ __forceinline__ int load_idx(const void* e, long long pos, int is64) {
    return is64 ? (int)((const long long*)e)[pos] : ((const int*)e)[pos];
}

__global__ void k_hist(const void* __restrict__ eidx) {              // launch 2
    int e = blockIdx.x * blockDim.x + threadIdx.x;
    if (e >= ET) return;
    int is64 = g_is64;
    int dst = (e < EE) ? load_idx(eidx, (long long)EE + e, is64) : (e - EE);
    atomicAdd(&g_deg[dst], 1);
}

__global__ void k_scan1() {                                          // launch 3
    __shared__ int wsum[32];
    int i = blockIdx.x * SCB + threadIdx.x;
    int lane = threadIdx.x & 31, wid = threadIdx.x >> 5;
    int v = (i < NN) ? g_deg[i] : 0;
#pragma unroll
    for (int o = 1; o < 32; o <<= 1) v += __shfl_down_sync(~0u, v, o);
    if (lane == 0) wsum[wid] = v;
    __syncthreads();
    if (wid == 0) {
        int s = wsum[lane];
#pragma unroll
        for (int o = 1; o < 32; o <<= 1) s += __shfl_down_sync(~0u, s, o);
        if (lane == 0) g_part[blockIdx.x] = s;
    }
}

__global__ void k_scan2() {                                          // launch 5
    __shared__ int wsum[32];
    __shared__ int sbase;
    int i = blockIdx.x * SCB + threadIdx.x;
    int lane = threadIdx.x & 31, wid = threadIdx.x >> 5;

    if (wid == 0) {
        int b = 0;
        for (int t = lane; t < NBLK; t += 32)
            if (t < blockIdx.x) b += g_part[t];
#pragma unroll
        for (int o = 1; o < 32; o <<= 1) b += __shfl_down_sync(~0u, b, o);
        if (lane == 0) sbase = b;
    }

    int v0 = (i < NN) ? g_deg[i] : 0;
    int v = v0;
#pragma unroll
    for (int o = 1; o < 32; o <<= 1) {
        int n = __shfl_up_sync(~0u, v, o);
        if (lane >= o) v += n;
    }
    if (lane == 31) wsum[wid] = v;
    __syncthreads();
    if (wid == 0) {
        int s = wsum[lane];
#pragma unroll
        for (int o = 1; o < 32; o <<= 1) {
            int n = __shfl_up_sync(~0u, s, o);
            if (lane >= o) s += n;
        }
        wsum[lane] = s;
    }
    __syncthreads();
    int excl = v - v0 + (wid ? wsum[wid - 1] : 0);
    if (i < NN) g_rowptr[i] = sbase + excl;
}

__global__ void k_scatter(const void* __restrict__ eidx) {           // launch 6
    int e = blockIdx.x * blockDim.x + threadIdx.x;
    if (e >= ET) return;
    int is64 = g_is64;
    int s, d;
    if (e < EE) {
        s = load_idx(eidx, e, is64);
        d = load_idx(eidx, (long long)EE + e, is64);
    } else {
        s = d = e - EE;
    }
    int pos = atomicAdd(&g_fill[d], 1);
    g_srcs[g_rowptr[d] + pos] = s;
}

// ---------------------------------------------------------------------------
// Persistent fused GEMM: xl = h @ Wl^T, xr = h @ Wr^T.
// 512 threads (4 warps/SMSP for latency hiding), thread tile 4 rows x 8 cols.
// ---------------------------------------------------------------------------
typedef unsigned long long u64;

__device__ __forceinline__ void ffma2(u64& acc, u64 a, u64 b) {
    asm("fma.rn.f32x2 %0, %1, %2, %0;" : "+l"(acc) : "l"(a), "l"(b));
}

__global__ void __launch_bounds__(GEMM_THREADS, 1)
k_gemm(const float* __restrict__ hin,
       const float* __restrict__ Wl,
       const float* __restrict__ Wr) {
    extern __shared__ float sm[];
    float* xs = sm;             // [TM][KP]
    float* ws = sm + TM * KP;   // [TN][KP]

    const int tid = threadIdx.x;
    const int lane = tid & 31;
    const int warp = tid >> 5;          // 0..15

    // Load W once (both matrices), row-major
    for (int idx = tid; idx < TN * 32; idx += GEMM_THREADS) {
        int r = idx >> 5, c4 = idx & 31;
        const float* wsrc = (r < DD) ? (Wl + (size_t)r * DD) : (Wr + (size_t)(r - DD) * DD);
        float4 g = *(const float4*)(wsrc + c4 * 4);
        *(float4*)(ws + r * KP + c4 * 4) = g;
    }

    const int warp_m = warp & 1;        // 0..1 : 32-row half
    const int warp_n = warp >> 1;       // 0..7 : 32-col group
    const int lane_m = lane >> 3;       // 0..3
    const int lane_n = lane & 7;        // 0..7
    const int rbase = warp_m * 32 + lane_m;   // rows rbase + 4*i, i<4... rows rbase+4i? see below
    const int jbase = warp_n * 32 + lane_n;   // cols jbase + 8*j, j<4
    const bool isL = (warp_n < 4);
    float* outp = isL ? g_xl : g_xr;
    const int cb = jbase - (isL ? 0 : DD);

    for (int tile = blockIdx.x; tile < NTILES; tile += GEMM_GRID) {
        const int row0 = tile * TM;

        for (int idx = tid; idx < TM * 32; idx += GEMM_THREADS) {
            int r = idx >> 5, c4 = idx & 31;
            int row = row0 + r;
            float4 g = make_float4(0.f, 0.f, 0.f, 0.f);
            if (row < NN) g = *(const float4*)(hin + (size_t)row * DD + c4 * 4);
            *(float4*)(xs + r * KP + c4 * 4) = g;
        }
        __syncthreads();

        // 8 rows (rbase + 4*i, i<8) x 4 cols (jbase + 8*j, j<4)
        u64 acc[8][4];
#pragma unroll
        for (int i = 0; i < 8; i++)
#pragma unroll
            for (int j = 0; j < 4; j++) acc[i][j] = 0ull;

        const float* xp = xs + rbase * KP;
        const float* wp = ws + jbase * KP;

#pragma unroll 1
        for (int k = 0; k < DD; k += 4) {
            ulonglong2 a2[8], b2[4];
#pragma unroll
            for (int j = 0; j < 4; j++)
                b2[j] = *(const ulonglong2*)(wp + j * 8 * KP + k);
#pragma unroll
            for (int i = 0; i < 8; i++)
                a2[i] = *(const ulonglong2*)(xp + i * 4 * KP + k);
#pragma unroll
            for (int i = 0; i < 8; i++)
#pragma unroll
                for (int j = 0; j < 4; j++) {
                    ffma2(acc[i][j], a2[i].x, b2[j].x);
                    ffma2(acc[i][j], a2[i].y, b2[j].y);
                }
        }
        __syncthreads();   // mainloop reads of xs done before next tile load

#pragma unroll
        for (int i = 0; i < 8; i++) {
            int row = row0 + rbase + i * 4;
            if (row < NN) {
                float* orow = outp + (size_t)row * DD;
#pragma unroll
                for (int j = 0; j < 4; j++) {
                    float2 s = *(float2*)&acc[i][j];
                    orow[cb + j * 8] = s.x + s.y;
                }
            }
        }
    }
}

// ---------------------------------------------------------------------------
// GATv2 aggregation: warp/node, online softmax, 4-edge ILP (round-3 proven).
// ---------------------------------------------------------------------------
__device__ __forceinline__ float gelu_exact(float x) {
    return 0.5f * x * (1.f + erff(x * 0.70710678118654752440f));
}

__device__ __forceinline__ float wsum32(float e) {
    e += __shfl_xor_sync(0xffffffffu, e, 16);
    e += __shfl_xor_sync(0xffffffffu, e, 8);
    e += __shfl_xor_sync(0xffffffffu, e, 4);
    e += __shfl_xor_sync(0xffffffffu, e, 2);
    e += __shfl_xor_sync(0xffffffffu, e, 1);
    return e;
}

__global__ void __launch_bounds__(256)
k_agg(const float* __restrict__ att,
      const float* __restrict__ bias,
      float* __restrict__ hout) {
    const int gw = (blockIdx.x * blockDim.x + threadIdx.x) >> 5;
    const int lane = threadIdx.x & 31;
    if (gw >= NN) return;
    const int d4 = lane * 4;

    const float4 xr4 = *(const float4*)(g_xr + (size_t)gw * DD + d4);
    const float4 at4 = *(const float4*)(att + d4);

    const int p0 = g_rowptr[gw];
    const int p1 = g_rowptr[gw + 1];

    float m = __int_as_float(0xff800000);  // -inf
    float denom = 0.f;
    float ax = 0.f, ay = 0.f, az = 0.f, aw = 0.f;

    int p = p0;
    for (; p + 4 <= p1; p += 4) {
        float4 v[4];
        float e[4];
#pragma unroll
        for (int q = 0; q < 4; q++) {
            int s = __ldg(&g_srcs[p + q]);
            v[q] = *(const float4*)(g_xl + (size_t)s * DD + d4);
            float t0 = v[q].x + xr4.x; t0 = t0 > 0.f ? t0 : 0.2f * t0;
            float t1 = v[q].y + xr4.y; t1 = t1 > 0.f ? t1 : 0.2f * t1;
            float t2 = v[q].z + xr4.z; t2 = t2 > 0.f ? t2 : 0.2f * t2;
            float t3 = v[q].w + xr4.w; t3 = t3 > 0.f ? t3 : 0.2f * t3;
            e[q] = t0 * at4.x + t1 * at4.y + t2 * at4.z + t3 * at4.w;
        }
#pragma unroll
        for (int q = 0; q < 4; q++) e[q] = wsum32(e[q]);
#pragma unroll
        for (int q = 0; q < 4; q++) {
            float mn = fmaxf(m, e[q]);
            float corr = __expf(m - mn);
            float w = __expf(e[q] - mn);
            denom = denom * corr + w;
            ax = ax * corr + w * v[q].x;
            ay = ay * corr + w * v[q].y;
            az = az * corr + w * v[q].z;
            aw = aw * corr + w * v[q].w;
            m = mn;
        }
    }
    for (; p < p1; p++) {
        int s = __ldg(&g_srcs[p]);
        const float4 vv = *(const float4*)(g_xl + (size_t)s * DD + d4);
        float t0 = vv.x + xr4.x; t0 = t0 > 0.f ? t0 : 0.2f * t0;
        float t1 = vv.y + xr4.y; t1 = t1 > 0.f ? t1 : 0.2f * t1;
        float t2 = vv.z + xr4.z; t2 = t2 > 0.f ? t2 : 0.2f * t2;
        float t3 = vv.w + xr4.w; t3 = t3 > 0.f ? t3 : 0.2f * t3;
        float e = wsum32(t0 * at4.x + t1 * at4.y + t2 * at4.z + t3 * at4.w);
        float mn = fmaxf(m, e);
        float corr = __expf(m - mn);
        float w = __expf(e - mn);
        denom = denom * corr + w;
        ax = ax * corr + w * vv.x;
        ay = ay * corr + w * vv.y;
        az = az * corr + w * vv.z;
        aw = aw * corr + w * vv.w;
        m = mn;
    }

    const float inv = 1.f / denom;
    const float4 b4 = *(const float4*)(bias + d4);
    float4 o;
    o.x = gelu_exact(ax * inv + b4.x);
    o.y = gelu_exact(ay * inv + b4.y);
    o.z = gelu_exact(az * inv + b4.z);
    o.w = gelu_exact(aw * inv + b4.w);
    *(float4*)(hout + (size_t)gw * DD + d4) = o;
}

// ---------------------------------------------------------------------------
extern "C" void kernel_launch(void* const* d_in, const int* in_sizes, int n_in,
                              void* d_out, int out_size) {
    const float* x = (const float*)d_in[0];
    const void* eidx = d_in[1];
    const float* Wl[3] = {(const float*)d_in[2], (const float*)d_in[6], (const float*)d_in[10]};
    const float* Wr[3] = {(const float*)d_in[3], (const float*)d_in[7], (const float*)d_in[11]};
    const float* at[3] = {(const float*)d_in[4], (const float*)d_in[8], (const float*)d_in[12]};
    const float* bi[3] = {(const float*)d_in[5], (const float*)d_in[9], (const float*)d_in[13]};

    void* p_h_v = nullptr;
    cudaGetSymbolAddress(&p_h_v, g_h);
    float* p_h = (float*)p_h_v;

    cudaFuncSetAttribute(k_gemm, cudaFuncAttributeMaxDynamicSharedMemorySize, GEMM_SMEM);

    // Launch order puts k_gemm (layer 0) at position 4 => it gets profiled.
    k_init<<<(NN + 255) / 256, 256>>>(eidx);                          // 1
    k_hist<<<(ET + 255) / 256, 256>>>(eidx);                          // 2
    k_scan1<<<NBLK, SCB>>>();                                         // 3
    k_gemm<<<GEMM_GRID, GEMM_THREADS, GEMM_SMEM>>>(x, Wl[0], Wr[0]);  // 4 (profiled)
    k_scan2<<<NBLK, SCB>>>();                                         // 5
    k_scatter<<<(ET + 255) / 256, 256>>>(eidx);                       // 6

    k_agg<<<(NN * 32 + 255) / 256, 256>>>(at[0], bi[0], p_h);         // 7

    for (int l = 1; l < 3; l++) {
        const float* hin = p_h;
        float* hout = (l == 2) ? (float*)d_out : p_h;
        k_gemm<<<GEMM_GRID, GEMM_THREADS, GEMM_SMEM>>>(hin, Wl[l], Wr[l]);
        k_agg<<<(NN * 32 + 255) / 256, 256>>>(at[l], bi[l], hout);
    }
}

// round 6
// speedup vs baseline: 1.5535x; 1.0911x over previous
#include <cuda_runtime.h>
#include <math.h>

#define NN 50000
#define DD 128
#define EE 800000
#define ET (EE + NN)

#define TM 64
#define TN 256
#define KP 132
#define NTILES ((NN + TM - 1) / TM)      // 782
#define GEMM_SMEM ((2 * TM + TN) * KP * 4)   // 202752 B
#define GEMM_GRID 148
#define GEMM_THREADS 512

#define SCB 1024
#define NBLK ((NN + SCB - 1) / SCB)

// Scratch (allocation-free rule: __device__ globals)
__device__ float g_xl[NN * DD];
__device__ float g_xr[NN * DD];
__device__ float g_h[NN * DD];
__device__ int g_rowptr[NN + 1];
__device__ int g_deg[NN];
__device__ int g_fill[NN];
__device__ int g_srcs[ET];
__device__ int g_part[NBLK];
__device__ int g_is64;

// ---------------------------------------------------------------------------
__global__ void k_init(const void* e) {
    int i = blockIdx.x * blockDim.x + threadIdx.x;
    if (i < NN) { g_deg[i] = 0; g_fill[i] = 0; }
    if (i == 0) {
        const long long* p = (const long long*)e;
        int ok = 1;
        for (int q = 0; q < 16; q++) {
            long long v = p[q];
            if (v < 0 || v >= NN) ok = 0;
        }
        g_is64 = ok;
        g_rowptr[NN] = ET;
    }
}

__device__ __forceinline__ int load_idx(const void* e, long long pos, int is64) {
    return is64 ? (int)((const long long*)e)[pos] : ((const int*)e)[pos];
}

__global__ void k_hist(const void* __restrict__ eidx) {
    int e = blockIdx.x * blockDim.x + threadIdx.x;
    if (e >= ET) return;
    int is64 = g_is64;
    int dst = (e < EE) ? load_idx(eidx, (long long)EE + e, is64) : (e - EE);
    atomicAdd(&g_deg[dst], 1);
}

__global__ void k_scan1() {
    __shared__ int wsum[32];
    int i = blockIdx.x * SCB + threadIdx.x;
    int lane = threadIdx.x & 31, wid = threadIdx.x >> 5;
    int v = (i < NN) ? g_deg[i] : 0;
#pragma unroll
    for (int o = 1; o < 32; o <<= 1) v += __shfl_down_sync(~0u, v, o);
    if (lane == 0) wsum[wid] = v;
    __syncthreads();
    if (wid == 0) {
        int s = wsum[lane];
#pragma unroll
        for (int o = 1; o < 32; o <<= 1) s += __shfl_down_sync(~0u, s, o);
        if (lane == 0) g_part[blockIdx.x] = s;
    }
}

__global__ void k_scan2() {
    __shared__ int wsum[32];
    __shared__ int sbase;
    int i = blockIdx.x * SCB + threadIdx.x;
    int lane = threadIdx.x & 31, wid = threadIdx.x >> 5;

    if (wid == 0) {
        int b = 0;
        for (int t = lane; t < NBLK; t += 32)
            if (t < blockIdx.x) b += g_part[t];
#pragma unroll
        for (int o = 1; o < 32; o <<= 1) b += __shfl_down_sync(~0u, b, o);
        if (lane == 0) sbase = b;
    }

    int v0 = (i < NN) ? g_deg[i] : 0;
    int v = v0;
#pragma unroll
    for (int o = 1; o < 32; o <<= 1) {
        int n = __shfl_up_sync(~0u, v, o);
        if (lane >= o) v += n;
    }
    if (lane == 31) wsum[wid] = v;
    __syncthreads();
    if (wid == 0) {
        int s = wsum[lane];
#pragma unroll
        for (int o = 1; o < 32; o <<= 1) {
            int n = __shfl_up_sync(~0u, s, o);
            if (lane >= o) s += n;
        }
        wsum[lane] = s;
    }
    __syncthreads();
    int excl = v - v0 + (wid ? wsum[wid - 1] : 0);
    if (i < NN) g_rowptr[i] = sbase + excl;
}

__global__ void k_scatter(const void* __restrict__ eidx) {
    int e = blockIdx.x * blockDim.x + threadIdx.x;
    if (e >= ET) return;
    int is64 = g_is64;
    int s, d;
    if (e < EE) {
        s = load_idx(eidx, e, is64);
        d = load_idx(eidx, (long long)EE + e, is64);
    } else {
        s = d = e - EE;
    }
    int pos = atomicAdd(&g_fill[d], 1);
    g_srcs[g_rowptr[d] + pos] = s;
}

// ---------------------------------------------------------------------------
// Persistent fused GEMM with cp.async double-buffered x tile.
// ---------------------------------------------------------------------------
typedef unsigned long long u64;

__device__ __forceinline__ void ffma2(u64& acc, u64 a, u64 b) {
    asm("fma.rn.f32x2 %0, %1, %2, %0;" : "+l"(acc) : "l"(a), "l"(b));
}

__device__ __forceinline__ void cp16(float* sdst, const float* gsrc) {
    unsigned sa = (unsigned)__cvta_generic_to_shared(sdst);
    asm volatile("cp.async.ca.shared.global [%0], [%1], 16;" :: "r"(sa), "l"(gsrc));
}

__device__ __forceinline__ void cp_commit() {
    asm volatile("cp.async.commit_group;");
}

__device__ __forceinline__ void cp_wait0() {
    asm volatile("cp.async.wait_group 0;");
}

__device__ __forceinline__ void tile_issue(float* xbuf, const float* hin,
                                           int row0, int tid) {
#pragma unroll
    for (int q = 0; q < 4; q++) {
        int idx = tid + q * GEMM_THREADS;          // < 2048 = TM*32
        int r = idx >> 5, c4 = idx & 31;
        int row = row0 + r;
        float* sd = xbuf + r * KP + c4 * 4;
        if (row < NN) {
            cp16(sd, hin + (size_t)row * DD + c4 * 4);
        } else {
            *(float4*)sd = make_float4(0.f, 0.f, 0.f, 0.f);
        }
    }
    cp_commit();
}

__global__ void __launch_bounds__(GEMM_THREADS, 1)
k_gemm(const float* __restrict__ hin,
       const float* __restrict__ Wl,
       const float* __restrict__ Wr) {
    extern __shared__ float sm[];
    float* xs0 = sm;                  // [TM][KP]
    float* xs1 = sm + TM * KP;        // [TM][KP]
    float* ws = sm + 2 * TM * KP;     // [TN][KP]

    const int tid = threadIdx.x;
    const int lane = tid & 31;
    const int warp = tid >> 5;

    // prologue: issue first tile's cp.async, then load W (LDG latency overlaps)
    int tile = blockIdx.x;
    if (tile < NTILES) tile_issue(xs0, hin, tile * TM, tid);

    for (int idx = tid; idx < TN * 32; idx += GEMM_THREADS) {
        int r = idx >> 5, c4 = idx & 31;
        const float* wsrc = (r < DD) ? (Wl + (size_t)r * DD) : (Wr + (size_t)(r - DD) * DD);
        float4 g = *(const float4*)(wsrc + c4 * 4);
        *(float4*)(ws + r * KP + c4 * 4) = g;
    }

    const int warp_m = warp & 1;
    const int warp_n = warp >> 1;
    const int lane_m = lane >> 3;
    const int lane_n = lane & 7;
    const int rbase = warp_m * 32 + lane_m;   // rows rbase + 4*i
    const int jbase = warp_n * 32 + lane_n;   // cols jbase + 8*j
    const bool isL = (warp_n < 4);
    float* outp = isL ? g_xl : g_xr;
    const int cb = jbase - (isL ? 0 : DD);

    int buf = 0;
    for (; tile < NTILES; tile += GEMM_GRID) {
        float* cur = buf ? xs1 : xs0;
        float* nxt = buf ? xs0 : xs1;

        cp_wait0();
        __syncthreads();          // cur ready; everyone done reading nxt

        int tnext = tile + GEMM_GRID;
        if (tnext < NTILES) tile_issue(nxt, hin, tnext * TM, tid);

        u64 acc[8][4];
#pragma unroll
        for (int i = 0; i < 8; i++)
#pragma unroll
            for (int j = 0; j < 4; j++) acc[i][j] = 0ull;

        const float* xp = cur + rbase * KP;
        const float* wp = ws + jbase * KP;

#pragma unroll 1
        for (int k = 0; k < DD; k += 4) {
            ulonglong2 a2[8], b2[4];
#pragma unroll
            for (int j = 0; j < 4; j++)
                b2[j] = *(const ulonglong2*)(wp + j * 8 * KP + k);
#pragma unroll
            for (int i = 0; i < 8; i++)
                a2[i] = *(const ulonglong2*)(xp + i * 4 * KP + k);
#pragma unroll
            for (int i = 0; i < 8; i++)
#pragma unroll
                for (int j = 0; j < 4; j++) {
                    ffma2(acc[i][j], a2[i].x, b2[j].x);
                    ffma2(acc[i][j], a2[i].y, b2[j].y);
                }
        }

        const int row0 = tile * TM;
#pragma unroll
        for (int i = 0; i < 8; i++) {
            int row = row0 + rbase + i * 4;
            if (row < NN) {
                float* orow = outp + (size_t)row * DD;
#pragma unroll
                for (int j = 0; j < 4; j++) {
                    float2 s = *(float2*)&acc[i][j];
                    orow[cb + j * 8] = s.x + s.y;
                }
            }
        }
        buf ^= 1;
    }
}

// ---------------------------------------------------------------------------
// GATv2 aggregation: warp/node, online softmax, 4-edge ILP (proven version).
// ---------------------------------------------------------------------------
__device__ __forceinline__ float gelu_exact(float x) {
    return 0.5f * x * (1.f + erff(x * 0.70710678118654752440f));
}

__device__ __forceinline__ float wsum32(float e) {
    e += __shfl_xor_sync(0xffffffffu, e, 16);
    e += __shfl_xor_sync(0xffffffffu, e, 8);
    e += __shfl_xor_sync(0xffffffffu, e, 4);
    e += __shfl_xor_sync(0xffffffffu, e, 2);
    e += __shfl_xor_sync(0xffffffffu, e, 1);
    return e;
}

__global__ void __launch_bounds__(256)
k_agg(const float* __restrict__ att,
      const float* __restrict__ bias,
      float* __restrict__ hout) {
    const int gw = (blockIdx.x * blockDim.x + threadIdx.x) >> 5;
    const int lane = threadIdx.x & 31;
    if (gw >= NN) return;
    const int d4 = lane * 4;

    const float4 xr4 = *(const float4*)(g_xr + (size_t)gw * DD + d4);
    const float4 at4 = *(const float4*)(att + d4);

    const int p0 = g_rowptr[gw];
    const int p1 = g_rowptr[gw + 1];

    float m = __int_as_float(0xff800000);  // -inf
    float denom = 0.f;
    float ax = 0.f, ay = 0.f, az = 0.f, aw = 0.f;

    int p = p0;
    for (; p + 4 <= p1; p += 4) {
        float4 v[4];
        float e[4];
#pragma unroll
        for (int q = 0; q < 4; q++) {
            int s = __ldg(&g_srcs[p + q]);
            v[q] = *(const float4*)(g_xl + (size_t)s * DD + d4);
            float t0 = v[q].x + xr4.x; t0 = t0 > 0.f ? t0 : 0.2f * t0;
            float t1 = v[q].y + xr4.y; t1 = t1 > 0.f ? t1 : 0.2f * t1;
            float t2 = v[q].z + xr4.z; t2 = t2 > 0.f ? t2 : 0.2f * t2;
            float t3 = v[q].w + xr4.w; t3 = t3 > 0.f ? t3 : 0.2f * t3;
            e[q] = t0 * at4.x + t1 * at4.y + t2 * at4.z + t3 * at4.w;
        }
#pragma unroll
        for (int q = 0; q < 4; q++) e[q] = wsum32(e[q]);
#pragma unroll
        for (int q = 0; q < 4; q++) {
            float mn = fmaxf(m, e[q]);
            float corr = __expf(m - mn);
            float w = __expf(e[q] - mn);
            denom = denom * corr + w;
            ax = ax * corr + w * v[q].x;
            ay = ay * corr + w * v[q].y;
            az = az * corr + w * v[q].z;
            aw = aw * corr + w * v[q].w;
            m = mn;
        }
    }
    for (; p < p1; p++) {
        int s = __ldg(&g_srcs[p]);
        const float4 vv = *(const float4*)(g_xl + (size_t)s * DD + d4);
        float t0 = vv.x + xr4.x; t0 = t0 > 0.f ? t0 : 0.2f * t0;
        float t1 = vv.y + xr4.y; t1 = t1 > 0.f ? t1 : 0.2f * t1;
        float t2 = vv.z + xr4.z; t2 = t2 > 0.f ? t2 : 0.2f * t2;
        float t3 = vv.w + xr4.w; t3 = t3 > 0.f ? t3 : 0.2f * t3;
        float e = wsum32(t0 * at4.x + t1 * at4.y + t2 * at4.z + t3 * at4.w);
        float mn = fmaxf(m, e);
        float corr = __expf(m - mn);
        float w = __expf(e - mn);
        denom = denom * corr + w;
        ax = ax * corr + w * vv.x;
        ay = ay * corr + w * vv.y;
        az = az * corr + w * vv.z;
        aw = aw * corr + w * vv.w;
        m = mn;
    }

    const float inv = 1.f / denom;
    const float4 b4 = *(const float4*)(bias + d4);
    float4 o;
    o.x = gelu_exact(ax * inv + b4.x);
    o.y = gelu_exact(ay * inv + b4.y);
    o.z = gelu_exact(az * inv + b4.z);
    o.w = gelu_exact(aw * inv + b4.w);
    *(float4*)(hout + (size_t)gw * DD + d4) = o;
}

// ---------------------------------------------------------------------------
extern "C" void kernel_launch(void* const* d_in, const int* in_sizes, int n_in,
                              void* d_out, int out_size) {
    const float* x = (const float*)d_in[0];
    const void* eidx = d_in[1];
    const float* Wl[3] = {(const float*)d_in[2], (const float*)d_in[6], (const float*)d_in[10]};
    const float* Wr[3] = {(const float*)d_in[3], (const float*)d_in[7], (const float*)d_in[11]};
    const float* at[3] = {(const float*)d_in[4], (const float*)d_in[8], (const float*)d_in[12]};
    const float* bi[3] = {(const float*)d_in[5], (const float*)d_in[9], (const float*)d_in[13]};

    void* p_h_v = nullptr;
    cudaGetSymbolAddress(&p_h_v, g_h);
    float* p_h = (float*)p_h_v;

    cudaFuncSetAttribute(k_gemm, cudaFuncAttributeMaxDynamicSharedMemorySize, GEMM_SMEM);

    // Fork: layer-0 GEMM (needs only x) runs concurrently with CSR build.
    cudaStream_t s2;
    cudaStreamCreateWithFlags(&s2, cudaStreamNonBlocking);
    cudaEvent_t ev_fork, ev_gemm;
    cudaEventCreateWithFlags(&ev_fork, cudaEventDisableTiming);
    cudaEventCreateWithFlags(&ev_gemm, cudaEventDisableTiming);

    cudaEventRecord(ev_fork, 0);
    cudaStreamWaitEvent(s2, ev_fork, 0);

    k_init<<<(NN + 255) / 256, 256>>>(eidx);                              // 1
    k_hist<<<(ET + 255) / 256, 256>>>(eidx);                              // 2
    k_scan1<<<NBLK, SCB>>>();                                             // 3
    k_gemm<<<GEMM_GRID, GEMM_THREADS, GEMM_SMEM, s2>>>(x, Wl[0], Wr[0]);  // 4 (profiled)
    k_scan2<<<NBLK, SCB>>>();                                             // 5
    k_scatter<<<(ET + 255) / 256, 256>>>(eidx);                           // 6

    cudaEventRecord(ev_gemm, s2);
    cudaStreamWaitEvent(0, ev_gemm, 0);

    k_agg<<<(NN * 32 + 255) / 256, 256>>>(at[0], bi[0], p_h);             // 7

    for (int l = 1; l < 3; l++) {
        const float* hin = p_h;
        float* hout = (l == 2) ? (float*)d_out : p_h;
        k_gemm<<<GEMM_GRID, GEMM_THREADS, GEMM_SMEM>>>(hin, Wl[l], Wr[l]);
        k_agg<<<(NN * 32 + 255) / 256, 256>>>(at[l], bi[l], hout);
    }

    cudaStreamDestroy(s2);
    cudaEventDestroy(ev_fork);
    cudaEventDestroy(ev_gemm);
}

// round 7
// speedup vs baseline: 1.5540x; 1.0003x over previous
#include <cuda_runtime.h>
#include <math.h>

#define NN 50000
#define DD 128
#define EE 800000
#define ET (EE + NN)

#define TM 32
#define TN 256
#define KP 132
#define NTILES ((NN + TM - 1) / TM)          // 1563
#define GEMM_SMEM ((2 * TM + TN) * KP * 4)   // 168960 B
#define GEMM_GRID 148
#define GEMM_THREADS 512

#define SCB 1024
#define NBLK ((NN + SCB - 1) / SCB)

// Scratch (allocation-free rule: __device__ globals)
__device__ float g_xl[NN * DD];
__device__ float g_xr[NN * DD];
__device__ float g_h[NN * DD];
__device__ int g_rowptr[NN + 1];
__device__ int g_deg[NN];
__device__ int g_fill[NN];
__device__ int g_srcs[ET];
__device__ int g_part[NBLK];
__device__ int g_is64;

// ---------------------------------------------------------------------------
__global__ void k_init(const void* e) {
    int i = blockIdx.x * blockDim.x + threadIdx.x;
    if (i < NN) { g_deg[i] = 0; g_fill[i] = 0; }
    if (i == 0) {
        const long long* p = (const long long*)e;
        int ok = 1;
        for (int q = 0; q < 16; q++) {
            long long v = p[q];
            if (v < 0 || v >= NN) ok = 0;
        }
        g_is64 = ok;
        g_rowptr[NN] = ET;
    }
}

__device__ __forceinline__ int load_idx(const void* e, long long pos, int is64) {
    return is64 ? (int)((const long long*)e)[pos] : ((const int*)e)[pos];
}

__global__ void k_hist(const void* __restrict__ eidx) {
    int e = blockIdx.x * blockDim.x + threadIdx.x;
    if (e >= ET) return;
    int is64 = g_is64;
    int dst = (e < EE) ? load_idx(eidx, (long long)EE + e, is64) : (e - EE);
    atomicAdd(&g_deg[dst], 1);
}

__global__ void k_scan1() {
    __shared__ int wsum[32];
    int i = blockIdx.x * SCB + threadIdx.x;
    int lane = threadIdx.x & 31, wid = threadIdx.x >> 5;
    int v = (i < NN) ? g_deg[i] : 0;
#pragma unroll
    for (int o = 1; o < 32; o <<= 1) v += __shfl_down_sync(~0u, v, o);
    if (lane == 0) wsum[wid] = v;
    __syncthreads();
    if (wid == 0) {
        int s = wsum[lane];
#pragma unroll
        for (int o = 1; o < 32; o <<= 1) s += __shfl_down_sync(~0u, s, o);
        if (lane == 0) g_part[blockIdx.x] = s;
    }
}

__global__ void k_scan2() {
    __shared__ int wsum[32];
    __shared__ int sbase;
    int i = blockIdx.x * SCB + threadIdx.x;
    int lane = threadIdx.x & 31, wid = threadIdx.x >> 5;

    if (wid == 0) {
        int b = 0;
        for (int t = lane; t < NBLK; t += 32)
            if (t < blockIdx.x) b += g_part[t];
#pragma unroll
        for (int o = 1; o < 32; o <<= 1) b += __shfl_down_sync(~0u, b, o);
        if (lane == 0) sbase = b;
    }

    int v0 = (i < NN) ? g_deg[i] : 0;
    int v = v0;
#pragma unroll
    for (int o = 1; o < 32; o <<= 1) {
        int n = __shfl_up_sync(~0u, v, o);
        if (lane >= o) v += n;
    }
    if (lane == 31) wsum[wid] = v;
    __syncthreads();
    if (wid == 0) {
        int s = wsum[lane];
#pragma unroll
        for (int o = 1; o < 32; o <<= 1) {
            int n = __shfl_up_sync(~0u, s, o);
            if (lane >= o) s += n;
        }
        wsum[lane] = s;
    }
    __syncthreads();
    int excl = v - v0 + (wid ? wsum[wid - 1] : 0);
    if (i < NN) g_rowptr[i] = sbase + excl;
}

__global__ void k_scatter(const void* __restrict__ eidx) {
    int e = blockIdx.x * blockDim.x + threadIdx.x;
    if (e >= ET) return;
    int is64 = g_is64;
    int s, d;
    if (e < EE) {
        s = load_idx(eidx, e, is64);
        d = load_idx(eidx, (long long)EE + e, is64);
    } else {
        s = d = e - EE;
    }
    int pos = atomicAdd(&g_fill[d], 1);
    g_srcs[g_rowptr[d] + pos] = s;
}

// ---------------------------------------------------------------------------
// Persistent fused GEMM, TM=32, thread tile 4x4, register double-buffered
// fragments (LDS for iter k+1 issued before FMAs of iter k).
// ---------------------------------------------------------------------------
typedef unsigned long long u64;

__device__ __forceinline__ void ffma2(u64& acc, u64 a, u64 b) {
    asm("fma.rn.f32x2 %0, %1, %2, %0;" : "+l"(acc) : "l"(a), "l"(b));
}

__device__ __forceinline__ void cp16(float* sdst, const float* gsrc) {
    unsigned sa = (unsigned)__cvta_generic_to_shared(sdst);
    asm volatile("cp.async.cg.shared.global [%0], [%1], 16;" :: "r"(sa), "l"(gsrc));
}

__device__ __forceinline__ void cp_commit() {
    asm volatile("cp.async.commit_group;");
}

__device__ __forceinline__ void cp_wait0() {
    asm volatile("cp.async.wait_group 0;");
}

__device__ __forceinline__ void tile_issue(float* xbuf, const float* hin,
                                           int row0, int tid) {
#pragma unroll
    for (int q = 0; q < 2; q++) {
        int idx = tid + q * GEMM_THREADS;          // < 1024 = TM*32
        int r = idx >> 5, c4 = idx & 31;
        int row = row0 + r;
        float* sd = xbuf + r * KP + c4 * 4;
        if (row < NN) {
            cp16(sd, hin + (size_t)row * DD + c4 * 4);
        } else {
            *(float4*)sd = make_float4(0.f, 0.f, 0.f, 0.f);
        }
    }
    cp_commit();
}

__global__ void __launch_bounds__(GEMM_THREADS, 1)
k_gemm(const float* __restrict__ hin,
       const float* __restrict__ Wl,
       const float* __restrict__ Wr) {
    extern __shared__ float sm[];
    float* xs0 = sm;                  // [TM][KP]
    float* xs1 = sm + TM * KP;        // [TM][KP]
    float* ws = sm + 2 * TM * KP;     // [TN][KP]

    const int tid = threadIdx.x;
    const int lane = tid & 31;
    const int warp = tid >> 5;        // 0..15

    int tile = blockIdx.x;
    if (tile < NTILES) tile_issue(xs0, hin, tile * TM, tid);

    for (int idx = tid; idx < TN * 32; idx += GEMM_THREADS) {
        int r = idx >> 5, c4 = idx & 31;
        const float* wsrc = (r < DD) ? (Wl + (size_t)r * DD) : (Wr + (size_t)(r - DD) * DD);
        float4 g = *(const float4*)(wsrc + c4 * 4);
        *(float4*)(ws + r * KP + c4 * 4) = g;
    }

    const int warp_m = warp & 1;        // 0..1 : 16-row half
    const int warp_n = warp >> 1;       // 0..7 : 32-col group
    const int lane_m = lane >> 3;       // 0..3
    const int lane_n = lane & 7;        // 0..7
    const int rbase = warp_m * 16 + lane_m;   // rows rbase + 4*i, i<4
    const int jbase = warp_n * 32 + lane_n;   // cols jbase + 8*j, j<4
    const bool isL = (warp_n < 4);
    float* outp = isL ? g_xl : g_xr;
    const int cb = jbase - (isL ? 0 : DD);

    int buf = 0;
    for (; tile < NTILES; tile += GEMM_GRID) {
        float* cur = buf ? xs1 : xs0;
        float* nxt = buf ? xs0 : xs1;

        cp_wait0();
        __syncthreads();

        int tnext = tile + GEMM_GRID;
        if (tnext < NTILES) tile_issue(nxt, hin, tnext * TM, tid);

        u64 acc[4][4];
#pragma unroll
        for (int i = 0; i < 4; i++)
#pragma unroll
            for (int j = 0; j < 4; j++) acc[i][j] = 0ull;

        const float* xp = cur + rbase * KP;
        const float* wp = ws + jbase * KP;

        // Register double-buffered fragments, fully unrolled K loop.
        ulonglong2 fa[2][4], fb[2][4];
#pragma unroll
        for (int i = 0; i < 4; i++) fa[0][i] = *(const ulonglong2*)(xp + i * 4 * KP);
#pragma unroll
        for (int j = 0; j < 4; j++) fb[0][j] = *(const ulonglong2*)(wp + j * 8 * KP);

#pragma unroll
        for (int kk = 0; kk < 32; kk++) {
            const int c = kk & 1, n = c ^ 1;
            if (kk < 31) {
                const int k = (kk + 1) * 4;
#pragma unroll
                for (int i = 0; i < 4; i++) fa[n][i] = *(const ulonglong2*)(xp + i * 4 * KP + k);
#pragma unroll
                for (int j = 0; j < 4; j++) fb[n][j] = *(const ulonglong2*)(wp + j * 8 * KP + k);
            }
#pragma unroll
            for (int i = 0; i < 4; i++)
#pragma unroll
                for (int j = 0; j < 4; j++) {
                    ffma2(acc[i][j], fa[c][i].x, fb[c][j].x);
                    ffma2(acc[i][j], fa[c][i].y, fb[c][j].y);
                }
        }

        const int row0 = tile * TM;
#pragma unroll
        for (int i = 0; i < 4; i++) {
            int row = row0 + rbase + i * 4;
            if (row < NN) {
                float* orow = outp + (size_t)row * DD;
#pragma unroll
                for (int j = 0; j < 4; j++) {
                    float2 s = *(float2*)&acc[i][j];
                    orow[cb + j * 8] = s.x + s.y;
                }
            }
        }
        buf ^= 1;
    }
}

// ---------------------------------------------------------------------------
// GATv2 aggregation: warp/node, online softmax, 4-edge ILP (proven version).
// ---------------------------------------------------------------------------
__device__ __forceinline__ float gelu_exact(float x) {
    return 0.5f * x * (1.f + erff(x * 0.70710678118654752440f));
}

__device__ __forceinline__ float wsum32(float e) {
    e += __shfl_xor_sync(0xffffffffu, e, 16);
    e += __shfl_xor_sync(0xffffffffu, e, 8);
    e += __shfl_xor_sync(0xffffffffu, e, 4);
    e += __shfl_xor_sync(0xffffffffu, e, 2);
    e += __shfl_xor_sync(0xffffffffu, e, 1);
    return e;
}

__global__ void __launch_bounds__(256)
k_agg(const float* __restrict__ att,
      const float* __restrict__ bias,
      float* __restrict__ hout) {
    const int gw = (blockIdx.x * blockDim.x + threadIdx.x) >> 5;
    const int lane = threadIdx.x & 31;
    if (gw >= NN) return;
    const int d4 = lane * 4;

    const float4 xr4 = *(const float4*)(g_xr + (size_t)gw * DD + d4);
    const float4 at4 = *(const float4*)(att + d4);

    const int p0 = g_rowptr[gw];
    const int p1 = g_rowptr[gw + 1];

    float m = __int_as_float(0xff800000);  // -inf
    float denom = 0.f;
    float ax = 0.f, ay = 0.f, az = 0.f, aw = 0.f;

    int p = p0;
    for (; p + 4 <= p1; p += 4) {
        float4 v[4];
        float e[4];
#pragma unroll
        for (int q = 0; q < 4; q++) {
            int s = __ldg(&g_srcs[p + q]);
            v[q] = *(const float4*)(g_xl + (size_t)s * DD + d4);
            float t0 = v[q].x + xr4.x; t0 = t0 > 0.f ? t0 : 0.2f * t0;
            float t1 = v[q].y + xr4.y; t1 = t1 > 0.f ? t1 : 0.2f * t1;
            float t2 = v[q].z + xr4.z; t2 = t2 > 0.f ? t2 : 0.2f * t2;
            float t3 = v[q].w + xr4.w; t3 = t3 > 0.f ? t3 : 0.2f * t3;
            e[q] = t0 * at4.x + t1 * at4.y + t2 * at4.z + t3 * at4.w;
        }
#pragma unroll
        for (int q = 0; q < 4; q++) e[q] = wsum32(e[q]);
#pragma unroll
        for (int q = 0; q < 4; q++) {
            float mn = fmaxf(m, e[q]);
            float corr = __expf(m - mn);
            float w = __expf(e[q] - mn);
            denom = denom * corr + w;
            ax = ax * corr + w * v[q].x;
            ay = ay * corr + w * v[q].y;
            az = az * corr + w * v[q].z;
            aw = aw * corr + w * v[q].w;
            m = mn;
        }
    }
    for (; p < p1; p++) {
        int s = __ldg(&g_srcs[p]);
        const float4 vv = *(const float4*)(g_xl + (size_t)s * DD + d4);
        float t0 = vv.x + xr4.x; t0 = t0 > 0.f ? t0 : 0.2f * t0;
        float t1 = vv.y + xr4.y; t1 = t1 > 0.f ? t1 : 0.2f * t1;
        float t2 = vv.z + xr4.z; t2 = t2 > 0.f ? t2 : 0.2f * t2;
        float t3 = vv.w + xr4.w; t3 = t3 > 0.f ? t3 : 0.2f * t3;
        float e = wsum32(t0 * at4.x + t1 * at4.y + t2 * at4.z + t3 * at4.w);
        float mn = fmaxf(m, e);
        float corr = __expf(m - mn);
        float w = __expf(e - mn);
        denom = denom * corr + w;
        ax = ax * corr + w * vv.x;
        ay = ay * corr + w * vv.y;
        az = az * corr + w * vv.z;
        aw = aw * corr + w * vv.w;
        m = mn;
    }

    const float inv = 1.f / denom;
    const float4 b4 = *(const float4*)(bias + d4);
    float4 o;
    o.x = gelu_exact(ax * inv + b4.x);
    o.y = gelu_exact(ay * inv + b4.y);
    o.z = gelu_exact(az * inv + b4.z);
    o.w = gelu_exact(aw * inv + b4.w);
    *(float4*)(hout + (size_t)gw * DD + d4) = o;
}

// ---------------------------------------------------------------------------
extern "C" void kernel_launch(void* const* d_in, const int* in_sizes, int n_in,
                              void* d_out, int out_size) {
    const float* x = (const float*)d_in[0];
    const void* eidx = d_in[1];
    const float* Wl[3] = {(const float*)d_in[2], (const float*)d_in[6], (const float*)d_in[10]};
    const float* Wr[3] = {(const float*)d_in[3], (const float*)d_in[7], (const float*)d_in[11]};
    const float* at[3] = {(const float*)d_in[4], (const float*)d_in[8], (const float*)d_in[12]};
    const float* bi[3] = {(const float*)d_in[5], (const float*)d_in[9], (const float*)d_in[13]};

    void* p_h_v = nullptr;
    cudaGetSymbolAddress(&p_h_v, g_h);
    float* p_h = (float*)p_h_v;

    cudaFuncSetAttribute(k_gemm, cudaFuncAttributeMaxDynamicSharedMemorySize, GEMM_SMEM);

    // Fork: layer-0 GEMM (needs only x) runs concurrently with CSR build.
    cudaStream_t s2;
    cudaStreamCreateWithFlags(&s2, cudaStreamNonBlocking);
    cudaEvent_t ev_fork, ev_gemm;
    cudaEventCreateWithFlags(&ev_fork, cudaEventDisableTiming);
    cudaEventCreateWithFlags(&ev_gemm, cudaEventDisableTiming);

    cudaEventRecord(ev_fork, 0);
    cudaStreamWaitEvent(s2, ev_fork, 0);

    k_init<<<(NN + 255) / 256, 256>>>(eidx);                              // 1
    k_hist<<<(ET + 255) / 256, 256>>>(eidx);                              // 2
    k_scan1<<<NBLK, SCB>>>();                                             // 3
    k_gemm<<<GEMM_GRID, GEMM_THREADS, GEMM_SMEM, s2>>>(x, Wl[0], Wr[0]);  // 4 (profiled)
    k_scan2<<<NBLK, SCB>>>();                                             // 5
    k_scatter<<<(ET + 255) / 256, 256>>>(eidx);                           // 6

    cudaEventRecord(ev_gemm, s2);
    cudaStreamWaitEvent(0, ev_gemm, 0);

    k_agg<<<(NN * 32 + 255) / 256, 256>>>(at[0], bi[0], p_h);             // 7

    for (int l = 1; l < 3; l++) {
        const float* hin = p_h;
        float* hout = (l == 2) ? (float*)d_out : p_h;
        k_gemm<<<GEMM_GRID, GEMM_THREADS, GEMM_SMEM>>>(hin, Wl[l], Wr[l]);
        k_agg<<<(NN * 32 + 255) / 256, 256>>>(at[l], bi[l], hout);
    }

    cudaStreamDestroy(s2);
    cudaEventDestroy(ev_fork);
    cudaEventDestroy(ev_gemm);
}

// round 11
// speedup vs baseline: 1.8099x; 1.1647x over previous
#include <cuda_runtime.h>
#include <cuda_bf16.h>
#include <mma.h>
#include <cstdint>
#include <stdint.h>
#include <math.h>

using namespace nvcuda;

#define NN 50000
#define DD 128
#define EE 800000
#define ET (EE + NN)

// ---- wmma bf16-split GEMM config ----
#define TM2 128
#define NT2 ((NN + TM2 - 1) / TM2)      // 391
#define GEMM_GRID 148
#define GEMM_THREADS 256
#define LDMH 136                         // smem pitch in bf16 elems (272B rows)

// smem byte offsets
#define SA_HI 0
#define SA_LO 34816
#define SB_HI_L 69632
#define SB_LO_L 104448
#define SB_HI_R 139264
#define SB_LO_R 174080
#define GEMM_SMEM 208896

#define SCB 1024
#define NBLK ((NN + SCB - 1) / SCB)

// Scratch (allocation-free rule: __device__ globals)
__device__ float g_xl[NN * DD];
__device__ float g_xr[NN * DD];
__device__ float g_h[NN * DD];
__device__ int g_rowptr[NN + 1];
__device__ int g_deg[NN];
__device__ int g_fill[NN];
__device__ int g_srcs[ET];
__device__ int g_part[NBLK];
__device__ int g_is64;

// ---------------------------------------------------------------------------
__global__ void k_init(const void* e) {
    int i = blockIdx.x * blockDim.x + threadIdx.x;
    if (i < NN) { g_deg[i] = 0; g_fill[i] = 0; }
    if (i == 0) {
        const long long* p = (const long long*)e;
        int ok = 1;
        for (int q = 0; q < 16; q++) {
            long long v = p[q];
            if (v < 0 || v >= NN) ok = 0;
        }
        g_is64 = ok;
        g_rowptr[NN] = ET;
    }
}

__device__ __forceinline__ int load_idx(const void* e, long long pos, int is64) {
    return is64 ? (int)((const long long*)e)[pos] : ((const int*)e)[pos];
}

__global__ void k_hist(const void* __restrict__ eidx) {
    int e = blockIdx.x * blockDim.x + threadIdx.x;
    if (e >= ET) return;
    int is64 = g_is64;
    int dst = (e < EE) ? load_idx(eidx, (long long)EE + e, is64) : (e - EE);
    atomicAdd(&g_deg[dst], 1);
}

__global__ void k_scan1() {
    __shared__ int wsum[32];
    int i = blockIdx.x * SCB + threadIdx.x;
    int lane = threadIdx.x & 31, wid = threadIdx.x >> 5;
    int v = (i < NN) ? g_deg[i] : 0;
#pragma unroll
    for (int o = 1; o < 32; o <<= 1) v += __shfl_down_sync(~0u, v, o);
    if (lane == 0) wsum[wid] = v;
    __syncthreads();
    if (wid == 0) {
        int s = wsum[lane];
#pragma unroll
        for (int o = 1; o < 32; o <<= 1) s += __shfl_down_sync(~0u, s, o);
        if (lane == 0) g_part[blockIdx.x] = s;
    }
}

__global__ void k_scan2() {
    __shared__ int wsum[32];
    __shared__ int sbase;
    int i = blockIdx.x * SCB + threadIdx.x;
    int lane = threadIdx.x & 31, wid = threadIdx.x >> 5;

    if (wid == 0) {
        int b = 0;
        for (int t = lane; t < NBLK; t += 32)
            if (t < blockIdx.x) b += g_part[t];
#pragma unroll
        for (int o = 1; o < 32; o <<= 1) b += __shfl_down_sync(~0u, b, o);
        if (lane == 0) sbase = b;
    }

    int v0 = (i < NN) ? g_deg[i] : 0;
    int v = v0;
#pragma unroll
    for (int o = 1; o < 32; o <<= 1) {
        int n = __shfl_up_sync(~0u, v, o);
        if (lane >= o) v += n;
    }
    if (lane == 31) wsum[wid] = v;
    __syncthreads();
    if (wid == 0) {
        int s = wsum[lane];
#pragma unroll
        for (int o = 1; o < 32; o <<= 1) {
            int n = __shfl_up_sync(~0u, s, o);
            if (lane >= o) s += n;
        }
        wsum[lane] = s;
    }
    __syncthreads();
    int excl = v - v0 + (wid ? wsum[wid - 1] : 0);
    if (i < NN) g_rowptr[i] = sbase + excl;
}

__global__ void k_scatter(const void* __restrict__ eidx) {
    int e = blockIdx.x * blockDim.x + threadIdx.x;
    if (e >= ET) return;
    int is64 = g_is64;
    int s, d;
    if (e < EE) {
        s = load_idx(eidx, e, is64);
        d = load_idx(eidx, (long long)EE + e, is64);
    } else {
        s = d = e - EE;
    }
    int pos = atomicAdd(&g_fill[d], 1);
    g_srcs[g_rowptr[d] + pos] = s;
}

// ---------------------------------------------------------------------------
// bf16 hi/lo split helpers
// ---------------------------------------------------------------------------
__device__ __forceinline__ uint32_t pack_hi(float x, float y, float& rx, float& ry) {
    __nv_bfloat16 bx = __float2bfloat16(x), by = __float2bfloat16(y);
    rx = x - __bfloat162float(bx);
    ry = y - __bfloat162float(by);
    return (uint32_t)__bfloat16_as_ushort(bx) | ((uint32_t)__bfloat16_as_ushort(by) << 16);
}
__device__ __forceinline__ uint32_t pack_lo(float rx, float ry) {
    return (uint32_t)__bfloat16_as_ushort(__float2bfloat16(rx)) |
           ((uint32_t)__bfloat16_as_ushort(__float2bfloat16(ry)) << 16);
}

// convert one 128x128 fp32 tile into bf16 hi/lo smem (row-major, pitch LDMH)
__device__ __forceinline__ void convA(char* smc, const float* hin, int row0,
                                      int t0, int nthr) {
    for (int idx = t0; idx < 4096; idx += nthr) {
        int r = idx >> 5;
        int c4 = (idx & 31) * 4;
        int row = row0 + r;
        float4 v = make_float4(0.f, 0.f, 0.f, 0.f);
        if (row < NN) v = *(const float4*)(hin + (size_t)row * DD + c4);
        float r0, r1, r2, r3;
        uint32_t h01 = pack_hi(v.x, v.y, r0, r1);
        uint32_t h23 = pack_hi(v.z, v.w, r2, r3);
        uint32_t l01 = pack_lo(r0, r1);
        uint32_t l23 = pack_lo(r2, r3);
        uint32_t off = (uint32_t)(r * LDMH + c4) * 2;
        *(uint64_t*)(smc + SA_HI + off) = (uint64_t)h01 | ((uint64_t)h23 << 32);
        *(uint64_t*)(smc + SA_LO + off) = (uint64_t)l01 | ((uint64_t)l23 << 32);
    }
}

// ---------------------------------------------------------------------------
// Persistent wmma GEMM: [g_xl | g_xr] = h @ [Wl | Wr]^T via bf16 3-split.
// Block: 256 threads (8 warps). Warp tile 32x64 per pass, 2 passes (L, R).
// ---------------------------------------------------------------------------
__global__ void __launch_bounds__(GEMM_THREADS, 1)
k_gemm(const float* __restrict__ hin,
       const float* __restrict__ Wl,
       const float* __restrict__ Wr) {
    extern __shared__ char smc[];
    const int tid = threadIdx.x;
    const int wid = tid >> 5;

    // W -> bf16 hi/lo (once per block); rows 0..127 = Wl, 128..255 = Wr
    for (int idx = tid; idx < 16384; idx += GEMM_THREADS) {
        int rfull = idx >> 6;              // 0..255
        int cp = (idx & 63) * 2;           // even col
        const float* wsrc = (rfull < DD) ? (Wl + (size_t)rfull * DD + cp)
                                         : (Wr + (size_t)(rfull - DD) * DD + cp);
        float2 v = *(const float2*)wsrc;
        float r0, r1;
        uint32_t hi = pack_hi(v.x, v.y, r0, r1);
        uint32_t lo = pack_lo(r0, r1);
        int rr = rfull & 127;
        uint32_t off = (uint32_t)(rr * LDMH + cp) * 2;
        char* bh = smc + ((rfull < DD) ? SB_HI_L : SB_HI_R);
        char* bl = smc + ((rfull < DD) ? SB_LO_L : SB_LO_R);
        *(uint32_t*)(bh + off) = hi;
        *(uint32_t*)(bl + off) = lo;
    }

    int tile = blockIdx.x;
    if (tile < NT2) convA(smc, hin, tile * TM2, tid, GEMM_THREADS);
    __syncthreads();

    const int m0w = (wid & 3) * 32;        // 4 warps along M
    const int n0w = (wid >> 2) * 64;       // 2 warps along N(half)

    const __nv_bfloat16* Ah = (const __nv_bfloat16*)(smc + SA_HI);
    const __nv_bfloat16* Al = (const __nv_bfloat16*)(smc + SA_LO);

    for (; tile < NT2; tile += GEMM_GRID) {
        const int row0 = tile * TM2;

#pragma unroll
        for (int pass = 0; pass < 2; pass++) {
            const __nv_bfloat16* Bh = (const __nv_bfloat16*)(smc + (pass ? SB_HI_R : SB_HI_L));
            const __nv_bfloat16* Bl = (const __nv_bfloat16*)(smc + (pass ? SB_LO_R : SB_LO_L));
            float* outp = pass ? g_xr : g_xl;

            wmma::fragment<wmma::accumulator, 16, 16, 16, float> acc[2][4];
#pragma unroll
            for (int i = 0; i < 2; i++)
#pragma unroll
                for (int n = 0; n < 4; n++) wmma::fill_fragment(acc[i][n], 0.f);

#pragma unroll
            for (int ks = 0; ks < 8; ks++) {
                const int k0 = ks * 16;
                wmma::fragment<wmma::matrix_a, 16, 16, 16, __nv_bfloat16, wmma::row_major> ah[2], al[2];
#pragma unroll
                for (int i = 0; i < 2; i++) {
                    wmma::load_matrix_sync(ah[i], Ah + (m0w + i * 16) * LDMH + k0, LDMH);
                    wmma::load_matrix_sync(al[i], Al + (m0w + i * 16) * LDMH + k0, LDMH);
                }
#pragma unroll
                for (int n = 0; n < 4; n++) {
                    wmma::fragment<wmma::matrix_b, 16, 16, 16, __nv_bfloat16, wmma::col_major> bh, bl;
                    wmma::load_matrix_sync(bh, Bh + (n0w + n * 16) * LDMH + k0, LDMH);
                    wmma::load_matrix_sync(bl, Bl + (n0w + n * 16) * LDMH + k0, LDMH);
#pragma unroll
                    for (int i = 0; i < 2; i++) {
                        wmma::mma_sync(acc[i][n], ah[i], bh, acc[i][n]);
                        wmma::mma_sync(acc[i][n], ah[i], bl, acc[i][n]);
                        wmma::mma_sync(acc[i][n], al[i], bh, acc[i][n]);
                    }
                }
            }

#pragma unroll
            for (int i = 0; i < 2; i++) {
                int row = row0 + m0w + i * 16;
                if (row + 16 <= NN) {
#pragma unroll
                    for (int n = 0; n < 4; n++)
                        wmma::store_matrix_sync(outp + (size_t)row * DD + n0w + n * 16,
                                                acc[i][n], DD, wmma::mem_row_major);
                }
            }
        }

        __syncthreads();   // all warps done reading A before overwrite
        int tnext = tile + GEMM_GRID;
        if (tnext < NT2) convA(smc, hin, tnext * TM2, tid, GEMM_THREADS);
        __syncthreads();
    }
}

// ---------------------------------------------------------------------------
// GATv2 aggregation: warp/node, online softmax, 4-edge ILP (proven version).
// ---------------------------------------------------------------------------
__device__ __forceinline__ float gelu_exact(float x) {
    return 0.5f * x * (1.f + erff(x * 0.70710678118654752440f));
}

__device__ __forceinline__ float wsum32(float e) {
    e += __shfl_xor_sync(0xffffffffu, e, 16);
    e += __shfl_xor_sync(0xffffffffu, e, 8);
    e += __shfl_xor_sync(0xffffffffu, e, 4);
    e += __shfl_xor_sync(0xffffffffu, e, 2);
    e += __shfl_xor_sync(0xffffffffu, e, 1);
    return e;
}

__global__ void __launch_bounds__(256)
k_agg(const float* __restrict__ att,
      const float* __restrict__ bias,
      float* __restrict__ hout) {
    const int gw = (blockIdx.x * blockDim.x + threadIdx.x) >> 5;
    const int lane = threadIdx.x & 31;
    if (gw >= NN) return;
    const int d4 = lane * 4;

    const float4 xr4 = *(const float4*)(g_xr + (size_t)gw * DD + d4);
    const float4 at4 = *(const float4*)(att + d4);

    const int p0 = g_rowptr[gw];
    const int p1 = g_rowptr[gw + 1];

    float m = __int_as_float(0xff800000);  // -inf
    float denom = 0.f;
    float ax = 0.f, ay = 0.f, az = 0.f, aw = 0.f;

    int p = p0;
    for (; p + 4 <= p1; p += 4) {
        float4 v[4];
        float e[4];
#pragma unroll
        for (int q = 0; q < 4; q++) {
            int s = __ldg(&g_srcs[p + q]);
            v[q] = *(const float4*)(g_xl + (size_t)s * DD + d4);
            float t0 = v[q].x + xr4.x; t0 = t0 > 0.f ? t0 : 0.2f * t0;
            float t1 = v[q].y + xr4.y; t1 = t1 > 0.f ? t1 : 0.2f * t1;
            float t2 = v[q].z + xr4.z; t2 = t2 > 0.f ? t2 : 0.2f * t2;
            float t3 = v[q].w + xr4.w; t3 = t3 > 0.f ? t3 : 0.2f * t3;
            e[q] = t0 * at4.x + t1 * at4.y + t2 * at4.z + t3 * at4.w;
        }
#pragma unroll
        for (int q = 0; q < 4; q++) e[q] = wsum32(e[q]);
#pragma unroll
        for (int q = 0; q < 4; q++) {
            float mn = fmaxf(m, e[q]);
            float corr = __expf(m - mn);
            float w = __expf(e[q] - mn);
            denom = denom * corr + w;
            ax = ax * corr + w * v[q].x;
            ay = ay * corr + w * v[q].y;
            az = az * corr + w * v[q].z;
            aw = aw * corr + w * v[q].w;
            m = mn;
        }
    }
    for (; p < p1; p++) {
        int s = __ldg(&g_srcs[p]);
        const float4 vv = *(const float4*)(g_xl + (size_t)s * DD + d4);
        float t0 = vv.x + xr4.x; t0 = t0 > 0.f ? t0 : 0.2f * t0;
        float t1 = vv.y + xr4.y; t1 = t1 > 0.f ? t1 : 0.2f * t1;
        float t2 = vv.z + xr4.z; t2 = t2 > 0.f ? t2 : 0.2f * t2;
        float t3 = vv.w + xr4.w; t3 = t3 > 0.f ? t3 : 0.2f * t3;
        float e = wsum32(t0 * at4.x + t1 * at4.y + t2 * at4.z + t3 * at4.w);
        float mn = fmaxf(m, e);
        float corr = __expf(m - mn);
        float w = __expf(e - mn);
        denom = denom * corr + w;
        ax = ax * corr + w * vv.x;
        ay = ay * corr + w * vv.y;
        az = az * corr + w * vv.z;
        aw = aw * corr + w * vv.w;
        m = mn;
    }

    const float inv = 1.f / denom;
    const float4 b4 = *(const float4*)(bias + d4);
    float4 o;
    o.x = gelu_exact(ax * inv + b4.x);
    o.y = gelu_exact(ay * inv + b4.y);
    o.z = gelu_exact(az * inv + b4.z);
    o.w = gelu_exact(aw * inv + b4.w);
    *(float4*)(hout + (size_t)gw * DD + d4) = o;
}

// ---------------------------------------------------------------------------
extern "C" void kernel_launch(void* const* d_in, const int* in_sizes, int n_in,
                              void* d_out, int out_size) {
    const float* x = (const float*)d_in[0];
    const void* eidx = d_in[1];
    const float* Wl[3] = {(const float*)d_in[2], (const float*)d_in[6], (const float*)d_in[10]};
    const float* Wr[3] = {(const float*)d_in[3], (const float*)d_in[7], (const float*)d_in[11]};
    const float* at[3] = {(const float*)d_in[4], (const float*)d_in[8], (const float*)d_in[12]};
    const float* bi[3] = {(const float*)d_in[5], (const float*)d_in[9], (const float*)d_in[13]};

    void* p_h_v = nullptr;
    cudaGetSymbolAddress(&p_h_v, g_h);
    float* p_h = (float*)p_h_v;

    cudaFuncSetAttribute(k_gemm, cudaFuncAttributeMaxDynamicSharedMemorySize, GEMM_SMEM);

    // Fork: layer-0 GEMM (needs only x) runs concurrently with CSR build.
    cudaStream_t s2;
    cudaStreamCreateWithFlags(&s2, cudaStreamNonBlocking);
    cudaEvent_t ev_fork, ev_gemm;
    cudaEventCreateWithFlags(&ev_fork, cudaEventDisableTiming);
    cudaEventCreateWithFlags(&ev_gemm, cudaEventDisableTiming);

    cudaEventRecord(ev_fork, 0);
    cudaStreamWaitEvent(s2, ev_fork, 0);

    k_init<<<(NN + 255) / 256, 256>>>(eidx);                              // 1
    k_hist<<<(ET + 255) / 256, 256>>>(eidx);                              // 2
    k_scan1<<<NBLK, SCB>>>();                                             // 3
    k_gemm<<<GEMM_GRID, GEMM_THREADS, GEMM_SMEM, s2>>>(x, Wl[0], Wr[0]);  // 4 (profiled)
    k_scan2<<<NBLK, SCB>>>();                                             // 5
    k_scatter<<<(ET + 255) / 256, 256>>>(eidx);                           // 6

    cudaEventRecord(ev_gemm, s2);
    cudaStreamWaitEvent(0, ev_gemm, 0);

    k_agg<<<(NN * 32 + 255) / 256, 256>>>(at[0], bi[0], p_h);             // 7

    for (int l = 1; l < 3; l++) {
        const float* hin = p_h;
        float* hout = (l == 2) ? (float*)d_out : p_h;
        k_gemm<<<GEMM_GRID, GEMM_THREADS, GEMM_SMEM>>>(hin, Wl[l], Wr[l]);
        k_agg<<<(NN * 32 + 255) / 256, 256>>>(at[l], bi[l], hout);
    }

    cudaStreamDestroy(s2);
    cudaEventDestroy(ev_fork);
    cudaEventDestroy(ev_gemm);
}

// round 12
// speedup vs baseline: 1.9720x; 1.0895x over previous
#include <cuda_runtime.h>
#include <cuda_bf16.h>
#include <mma.h>
#include <cstdint>
#include <stdint.h>
#include <math.h>

using namespace nvcuda;

#define NN 50000
#define DD 128
#define EE 800000
#define ET (EE + NN)

// ---- wmma bf16-split GEMM config ----
#define TM2 64
#define NT2 ((NN + TM2 - 1) / TM2)      // 782
#define GEMM_GRID 148
#define GEMM_THREADS 512
#define LDMH 136                         // smem pitch in bf16 elems (272B rows)
#define A_BUF_B 17408                    // 64*136*2
#define W_BUF_B 34816                    // 128*136*2

// smem byte offsets
#define SA0 0
#define SW0 69632                        // after 4 A buffers (hi0,lo0,hi1,lo1)
#define GEMM_SMEM 208896                 // 69632 + 4*34816

#define SCB 1024
#define NBLK ((NN + SCB - 1) / SCB)

// Scratch (allocation-free rule: __device__ globals)
__device__ float g_xl[NN * DD];
__device__ float g_xr[NN * DD];
__device__ __nv_bfloat16 g_hbh[NN * DD];
__device__ __nv_bfloat16 g_hbl[NN * DD];
__device__ int g_rowptr[NN + 1];
__device__ int g_deg[NN];
__device__ int g_fill[NN];
__device__ int g_srcs[ET];
__device__ int g_part[NBLK];
__device__ int g_is64;

// ---------------------------------------------------------------------------
__global__ void k_init(const void* e) {
    int i = blockIdx.x * blockDim.x + threadIdx.x;
    if (i < NN) { g_deg[i] = 0; g_fill[i] = 0; }
    if (i == 0) {
        const long long* p = (const long long*)e;
        int ok = 1;
        for (int q = 0; q < 16; q++) {
            long long v = p[q];
            if (v < 0 || v >= NN) ok = 0;
        }
        g_is64 = ok;
        g_rowptr[NN] = ET;
    }
}

__device__ __forceinline__ int load_idx(const void* e, long long pos, int is64) {
    return is64 ? (int)((const long long*)e)[pos] : ((const int*)e)[pos];
}

__global__ void k_hist(const void* __restrict__ eidx) {
    int e = blockIdx.x * blockDim.x + threadIdx.x;
    if (e >= ET) return;
    int is64 = g_is64;
    int dst = (e < EE) ? load_idx(eidx, (long long)EE + e, is64) : (e - EE);
    atomicAdd(&g_deg[dst], 1);
}

__global__ void k_scan1() {
    __shared__ int wsum[32];
    int i = blockIdx.x * SCB + threadIdx.x;
    int lane = threadIdx.x & 31, wid = threadIdx.x >> 5;
    int v = (i < NN) ? g_deg[i] : 0;
#pragma unroll
    for (int o = 1; o < 32; o <<= 1) v += __shfl_down_sync(~0u, v, o);
    if (lane == 0) wsum[wid] = v;
    __syncthreads();
    if (wid == 0) {
        int s = wsum[lane];
#pragma unroll
        for (int o = 1; o < 32; o <<= 1) s += __shfl_down_sync(~0u, s, o);
        if (lane == 0) g_part[blockIdx.x] = s;
    }
}

__global__ void k_scan2() {
    __shared__ int wsum[32];
    __shared__ int sbase;
    int i = blockIdx.x * SCB + threadIdx.x;
    int lane = threadIdx.x & 31, wid = threadIdx.x >> 5;

    if (wid == 0) {
        int b = 0;
        for (int t = lane; t < NBLK; t += 32)
            if (t < blockIdx.x) b += g_part[t];
#pragma unroll
        for (int o = 1; o < 32; o <<= 1) b += __shfl_down_sync(~0u, b, o);
        if (lane == 0) sbase = b;
    }

    int v0 = (i < NN) ? g_deg[i] : 0;
    int v = v0;
#pragma unroll
    for (int o = 1; o < 32; o <<= 1) {
        int n = __shfl_up_sync(~0u, v, o);
        if (lane >= o) v += n;
    }
    if (lane == 31) wsum[wid] = v;
    __syncthreads();
    if (wid == 0) {
        int s = wsum[lane];
#pragma unroll
        for (int o = 1; o < 32; o <<= 1) {
            int n = __shfl_up_sync(~0u, s, o);
            if (lane >= o) s += n;
        }
        wsum[lane] = s;
    }
    __syncthreads();
    int excl = v - v0 + (wid ? wsum[wid - 1] : 0);
    if (i < NN) g_rowptr[i] = sbase + excl;
}

__global__ void k_scatter(const void* __restrict__ eidx) {
    int e = blockIdx.x * blockDim.x + threadIdx.x;
    if (e >= ET) return;
    int is64 = g_is64;
    int s, d;
    if (e < EE) {
        s = load_idx(eidx, e, is64);
        d = load_idx(eidx, (long long)EE + e, is64);
    } else {
        s = d = e - EE;
    }
    int pos = atomicAdd(&g_fill[d], 1);
    g_srcs[g_rowptr[d] + pos] = s;
}

// ---------------------------------------------------------------------------
// bf16 hi/lo split helpers
// ---------------------------------------------------------------------------
__device__ __forceinline__ uint32_t pack_hi(float x, float y, float& rx, float& ry) {
    __nv_bfloat16 bx = __float2bfloat16(x), by = __float2bfloat16(y);
    rx = x - __bfloat162float(bx);
    ry = y - __bfloat162float(by);
    return (uint32_t)__bfloat16_as_ushort(bx) | ((uint32_t)__bfloat16_as_ushort(by) << 16);
}
__device__ __forceinline__ uint32_t pack_lo(float rx, float ry) {
    return (uint32_t)__bfloat16_as_ushort(__float2bfloat16(rx)) |
           ((uint32_t)__bfloat16_as_ushort(__float2bfloat16(ry)) << 16);
}

// Convert fp32 feature matrix -> bf16 hi/lo global arrays (layer-0 input)
__global__ void k_convx(const float* __restrict__ src) {
    int idx = blockIdx.x * blockDim.x + threadIdx.x;     // one float4 each
    if (idx >= NN * DD / 4) return;
    float4 v = *(const float4*)(src + (size_t)idx * 4);
    float r0, r1, r2, r3;
    uint32_t h01 = pack_hi(v.x, v.y, r0, r1);
    uint32_t h23 = pack_hi(v.z, v.w, r2, r3);
    uint2 hv; hv.x = h01; hv.y = h23;
    uint2 lv; lv.x = pack_lo(r0, r1); lv.y = pack_lo(r2, r3);
    *(uint2*)((char*)g_hbh + (size_t)idx * 8) = hv;
    *(uint2*)((char*)g_hbl + (size_t)idx * 8) = lv;
}

// ---------------------------------------------------------------------------
// cp.async helpers
// ---------------------------------------------------------------------------
__device__ __forceinline__ void cp16(void* sdst, const void* gsrc) {
    unsigned sa = (unsigned)__cvta_generic_to_shared(sdst);
    asm volatile("cp.async.ca.shared.global [%0], [%1], 16;" :: "r"(sa), "l"(gsrc));
}
__device__ __forceinline__ void cp_commit() { asm volatile("cp.async.commit_group;"); }
__device__ __forceinline__ void cp_wait0() { asm volatile("cp.async.wait_group 0;"); }

// issue cp.async for one 64x128 bf16 hi+lo A tile into buffer `buf`
__device__ __forceinline__ void issueA(char* smc, int buf, int row0, int tid) {
#pragma unroll
    for (int q = 0; q < 4; q++) {
        int idx = tid + q * GEMM_THREADS;     // 0..2047
        int half = idx >> 10;                 // 0 = hi, 1 = lo
        int rc = idx & 1023;
        int r = rc >> 4, c = rc & 15;         // row 0..63, 16B chunk 0..15
        int row = row0 + r;
        char* dst = smc + SA0 + buf * (2 * A_BUF_B) + half * A_BUF_B + r * 272 + c * 16;
        if (row < NN) {
            const __nv_bfloat16* src = (half ? g_hbl : g_hbh) + (size_t)row * DD + c * 8;
            cp16(dst, src);
        } else {
            *(uint4*)dst = make_uint4(0, 0, 0, 0);
        }
    }
    cp_commit();
}

// ---------------------------------------------------------------------------
// Persistent wmma GEMM: [g_xl | g_xr] = h @ [Wl | Wr]^T via bf16 3-split.
// A pre-split in global (g_hbh/g_hbl); double-buffered cp.async A tiles.
// 512 threads = 16 warps; warp tile 16 x 64.
// ---------------------------------------------------------------------------
__global__ void __launch_bounds__(GEMM_THREADS, 1)
k_gemm(const float* __restrict__ Wl, const float* __restrict__ Wr) {
    extern __shared__ char smc[];
    const int tid = threadIdx.x;
    const int wid = tid >> 5;

    int tile = blockIdx.x;
    if (tile < NT2) issueA(smc, 0, tile * TM2, tid);

    // W -> bf16 hi/lo (once per block): region order hiL, loL, hiR, loR
    for (int idx = tid; idx < 16384; idx += GEMM_THREADS) {
        int rfull = idx >> 6;              // 0..255
        int cp = (idx & 63) * 2;           // even col
        const float* wsrc = (rfull < DD) ? (Wl + (size_t)rfull * DD + cp)
                                         : (Wr + (size_t)(rfull - DD) * DD + cp);
        float2 v = *(const float2*)wsrc;
        float r0, r1;
        uint32_t hi = pack_hi(v.x, v.y, r0, r1);
        uint32_t lo = pack_lo(r0, r1);
        int rr = rfull & 127;
        uint32_t off = (uint32_t)(rr * LDMH + cp) * 2;
        char* base = smc + SW0 + ((rfull < DD) ? 0 : 2 * W_BUF_B);
        *(uint32_t*)(base + off) = hi;
        *(uint32_t*)(base + W_BUF_B + off) = lo;
    }

    const int m0 = (wid & 3) * 16;         // 4 warps along M (64 rows)
    const int n0 = (wid >> 2) * 64;        // 4 warps along N (256 cols)

    int buf = 0;
    for (; tile < NT2; tile += GEMM_GRID) {
        const int row0 = tile * TM2;

        cp_wait0();
        __syncthreads();                   // A[buf] ready; prior reads of other buf done

        int tnext = tile + GEMM_GRID;
        if (tnext < NT2) issueA(smc, buf ^ 1, tnext * TM2, tid);

        const __nv_bfloat16* Ah = (const __nv_bfloat16*)(smc + SA0 + buf * (2 * A_BUF_B));
        const __nv_bfloat16* Al = (const __nv_bfloat16*)((const char*)Ah + A_BUF_B);

        wmma::fragment<wmma::accumulator, 16, 16, 16, float> acc[4];
#pragma unroll
        for (int n = 0; n < 4; n++) wmma::fill_fragment(acc[n], 0.f);

#pragma unroll
        for (int ks = 0; ks < 8; ks++) {
            const int k0 = ks * 16;
            wmma::fragment<wmma::matrix_a, 16, 16, 16, __nv_bfloat16, wmma::row_major> ah, al;
            wmma::load_matrix_sync(ah, Ah + m0 * LDMH + k0, LDMH);
            wmma::load_matrix_sync(al, Al + m0 * LDMH + k0, LDMH);
#pragma unroll
            for (int n = 0; n < 4; n++) {
                const int col = n0 + n * 16;
                const char* wb = smc + SW0 + ((col < DD) ? 0 : 2 * W_BUF_B);
                const int lc = col & 127;
                wmma::fragment<wmma::matrix_b, 16, 16, 16, __nv_bfloat16, wmma::col_major> bh, bl;
                wmma::load_matrix_sync(bh, (const __nv_bfloat16*)wb + lc * LDMH + k0, LDMH);
                wmma::load_matrix_sync(bl, (const __nv_bfloat16*)(wb + W_BUF_B) + lc * LDMH + k0, LDMH);
                wmma::mma_sync(acc[n], ah, bh, acc[n]);
                wmma::mma_sync(acc[n], ah, bl, acc[n]);
                wmma::mma_sync(acc[n], al, bh, acc[n]);
            }
        }

        int row = row0 + m0;
        if (row + 16 <= NN) {
#pragma unroll
            for (int n = 0; n < 4; n++) {
                const int col = n0 + n * 16;
                float* outp = (col < DD) ? (g_xl + (size_t)row * DD + col)
                                         : (g_xr + (size_t)row * DD + (col - DD));
                wmma::store_matrix_sync(outp, acc[n], DD, wmma::mem_row_major);
            }
        }
        buf ^= 1;
    }
}

// ---------------------------------------------------------------------------
// GATv2 aggregation: warp/node, online softmax, 4-edge ILP.
// Epilogue writes either fp32 (final layer) or bf16 hi/lo (next-layer input).
// ---------------------------------------------------------------------------
__device__ __forceinline__ float gelu_exact(float x) {
    return 0.5f * x * (1.f + erff(x * 0.70710678118654752440f));
}

__device__ __forceinline__ float wsum32(float e) {
    e += __shfl_xor_sync(0xffffffffu, e, 16);
    e += __shfl_xor_sync(0xffffffffu, e, 8);
    e += __shfl_xor_sync(0xffffffffu, e, 4);
    e += __shfl_xor_sync(0xffffffffu, e, 2);
    e += __shfl_xor_sync(0xffffffffu, e, 1);
    return e;
}

__global__ void __launch_bounds__(256)
k_agg(const float* __restrict__ att,
      const float* __restrict__ bias,
      float* __restrict__ houtf) {        // non-null: fp32 out; null: bf16 split out
    const int gw = (blockIdx.x * blockDim.x + threadIdx.x) >> 5;
    const int lane = threadIdx.x & 31;
    if (gw >= NN) return;
    const int d4 = lane * 4;

    const float4 xr4 = *(const float4*)(g_xr + (size_t)gw * DD + d4);
    const float4 at4 = *(const float4*)(att + d4);

    const int p0 = g_rowptr[gw];
    const int p1 = g_rowptr[gw + 1];

    float m = __int_as_float(0xff800000);  // -inf
    float denom = 0.f;
    float ax = 0.f, ay = 0.f, az = 0.f, aw = 0.f;

    int p = p0;
    for (; p + 4 <= p1; p += 4) {
        float4 v[4];
        float e[4];
#pragma unroll
        for (int q = 0; q < 4; q++) {
            int s = __ldg(&g_srcs[p + q]);
            v[q] = *(const float4*)(g_xl + (size_t)s * DD + d4);
            float t0 = v[q].x + xr4.x; t0 = t0 > 0.f ? t0 : 0.2f * t0;
            float t1 = v[q].y + xr4.y; t1 = t1 > 0.f ? t1 : 0.2f * t1;
            float t2 = v[q].z + xr4.z; t2 = t2 > 0.f ? t2 : 0.2f * t2;
            float t3 = v[q].w + xr4.w; t3 = t3 > 0.f ? t3 : 0.2f * t3;
            e[q] = t0 * at4.x + t1 * at4.y + t2 * at4.z + t3 * at4.w;
        }
#pragma unroll
        for (int q = 0; q < 4; q++) e[q] = wsum32(e[q]);
#pragma unroll
        for (int q = 0; q < 4; q++) {
            float mn = fmaxf(m, e[q]);
            float corr = __expf(m - mn);
            float w = __expf(e[q] - mn);
            denom = denom * corr + w;
            ax = ax * corr + w * v[q].x;
            ay = ay * corr + w * v[q].y;
            az = az * corr + w * v[q].z;
            aw = aw * corr + w * v[q].w;
            m = mn;
        }
    }
    for (; p < p1; p++) {
        int s = __ldg(&g_srcs[p]);
        const float4 vv = *(const float4*)(g_xl + (size_t)s * DD + d4);
        float t0 = vv.x + xr4.x; t0 = t0 > 0.f ? t0 : 0.2f * t0;
        float t1 = vv.y + xr4.y; t1 = t1 > 0.f ? t1 : 0.2f * t1;
        float t2 = vv.z + xr4.z; t2 = t2 > 0.f ? t2 : 0.2f * t2;
        float t3 = vv.w + xr4.w; t3 = t3 > 0.f ? t3 : 0.2f * t3;
        float e = wsum32(t0 * at4.x + t1 * at4.y + t2 * at4.z + t3 * at4.w);
        float mn = fmaxf(m, e);
        float corr = __expf(m - mn);
        float w = __expf(e - mn);
        denom = denom * corr + w;
        ax = ax * corr + w * vv.x;
        ay = ay * corr + w * vv.y;
        az = az * corr + w * vv.z;
        aw = aw * corr + w * vv.w;
        m = mn;
    }

    const float inv = 1.f / denom;
    const float4 b4 = *(const float4*)(bias + d4);
    float4 o;
    o.x = gelu_exact(ax * inv + b4.x);
    o.y = gelu_exact(ay * inv + b4.y);
    o.z = gelu_exact(az * inv + b4.z);
    o.w = gelu_exact(aw * inv + b4.w);

    if (houtf) {
        *(float4*)(houtf + (size_t)gw * DD + d4) = o;
    } else {
        float r0, r1, r2, r3;
        uint2 hv, lv;
        hv.x = pack_hi(o.x, o.y, r0, r1);
        hv.y = pack_hi(o.z, o.w, r2, r3);
        lv.x = pack_lo(r0, r1);
        lv.y = pack_lo(r2, r3);
        *(uint2*)((char*)g_hbh + ((size_t)gw * DD + d4) * 2) = hv;
        *(uint2*)((char*)g_hbl + ((size_t)gw * DD + d4) * 2) = lv;
    }
}

// ---------------------------------------------------------------------------
extern "C" void kernel_launch(void* const* d_in, const int* in_sizes, int n_in,
                              void* d_out, int out_size) {
    const float* x = (const float*)d_in[0];
    const void* eidx = d_in[1];
    const float* Wl[3] = {(const float*)d_in[2], (const float*)d_in[6], (const float*)d_in[10]};
    const float* Wr[3] = {(const float*)d_in[3], (const float*)d_in[7], (const float*)d_in[11]};
    const float* at[3] = {(const float*)d_in[4], (const float*)d_in[8], (const float*)d_in[12]};
    const float* bi[3] = {(const float*)d_in[5], (const float*)d_in[9], (const float*)d_in[13]};

    cudaFuncSetAttribute(k_gemm, cudaFuncAttributeMaxDynamicSharedMemorySize, GEMM_SMEM);

    // Fork: layer-0 conv+GEMM (needs only x) runs concurrently with CSR build.
    cudaStream_t s2;
    cudaStreamCreateWithFlags(&s2, cudaStreamNonBlocking);
    cudaEvent_t ev_fork, ev_gemm;
    cudaEventCreateWithFlags(&ev_fork, cudaEventDisableTiming);
    cudaEventCreateWithFlags(&ev_gemm, cudaEventDisableTiming);

    cudaEventRecord(ev_fork, 0);
    cudaStreamWaitEvent(s2, ev_fork, 0);

    k_convx<<<(NN * DD / 4 + 255) / 256, 256, 0, s2>>>(x);             // 1
    k_init<<<(NN + 255) / 256, 256>>>(eidx);                           // 2
    k_hist<<<(ET + 255) / 256, 256>>>(eidx);                           // 3
    k_gemm<<<GEMM_GRID, GEMM_THREADS, GEMM_SMEM, s2>>>(Wl[0], Wr[0]);  // 4 (profiled)
    k_scan1<<<NBLK, SCB>>>();                                          // 5
    k_scan2<<<NBLK, SCB>>>();                                          // 6
    k_scatter<<<(ET + 255) / 256, 256>>>(eidx);                        // 7

    cudaEventRecord(ev_gemm, s2);
    cudaStreamWaitEvent(0, ev_gemm, 0);

    k_agg<<<(NN * 32 + 255) / 256, 256>>>(at[0], bi[0], nullptr);      // -> g_hbh/g_hbl

    for (int l = 1; l < 3; l++) {
        float* houtf = (l == 2) ? (float*)d_out : nullptr;
        k_gemm<<<GEMM_GRID, GEMM_THREADS, GEMM_SMEM>>>(Wl[l], Wr[l]);
        k_agg<<<(NN * 32 + 255) / 256, 256>>>(at[l], bi[l], houtf);
    }

    cudaStreamDestroy(s2);
    cudaEventDestroy(ev_fork);
    cudaEventDestroy(ev_gemm);
}